// round 1
// baseline (speedup 1.0000x reference)
#include <cuda_runtime.h>
#include <math.h>

#define NNODE 100000
#define DIN   256
#define C1    128   // H1*HID (2 heads x 64)
#define C2    64    // layer-2 channels

// ---------------- device scratch (no allocations allowed) ----------------
static __device__ __align__(16) float g_h1 [(size_t)NNODE * C1];  // x @ W1
static __device__ __align__(16) float g_out1[(size_t)NNODE * C1]; // layer1 accum -> h2 (in place)
static __device__ __align__(16) float g_h3 [(size_t)NNODE * C2];  // h2 @ W2
static __device__ float g_als1[NNODE * 2];
static __device__ float g_ald1[NNODE * 2];
static __device__ float g_m1 [NNODE * 2];
static __device__ float g_z1 [NNODE * 2];
static __device__ float g_als2[NNODE];
static __device__ float g_ald2[NNODE];
static __device__ float g_m2 [NNODE];
static __device__ float g_z2 [NNODE];

__device__ __forceinline__ void atomicMaxF(float* a, float v) {
    // order-preserving: non-negative -> signed int max, negative -> unsigned min
    if (v >= 0.f) atomicMax((int*)a, __float_as_int(v));
    else          atomicMin((unsigned int*)a, __float_as_uint(v));
}

__device__ __forceinline__ float leaky(float v) { return v > 0.f ? v : 0.2f * v; }

// ---------------- init: zeros + (-inf) maxima ----------------
__global__ void init_kernel(float* __restrict__ out_acc) {
    int i = blockIdx.x * blockDim.x + threadIdx.x;
    const float NEG_INF = __int_as_float(0xFF800000);
    if (i < NNODE * C1) g_out1[i] = 0.f;
    if (i < NNODE * C2) out_acc[i] = 0.f;
    if (i < NNODE * 2) { g_m1[i] = NEG_INF; g_z1[i] = 0.f; }
    if (i < NNODE)     { g_m2[i] = NEG_INF; g_z2[i] = 0.f; }
}

// ---------------- row-blocked fp32 GEMM: Y[M,NC] = X[M,K] @ W[K,NC] ----------------
// one warp computes 4 rows; lane owns VEC consecutive output columns.
template<int K, int VEC>
__global__ void __launch_bounds__(256) gemm_rows(const float* __restrict__ X,
                                                 const float* __restrict__ W,
                                                 float* __restrict__ Y, int M) {
    constexpr int NC = 32 * VEC;
    int warp = (int)((blockIdx.x * blockDim.x + threadIdx.x) >> 5);
    int lane = threadIdx.x & 31;
    int r0 = warp * 4;
    if (r0 >= M) return;

    float xr[4][K / 32];
#pragma unroll
    for (int r = 0; r < 4; r++) {
        int row = r0 + r; if (row > M - 1) row = M - 1;   // clamp; stores guarded below
        const float* xp = X + (size_t)row * K;
#pragma unroll
        for (int i = 0; i < K / 32; i++) xr[r][i] = __ldg(xp + i * 32 + lane);
    }

    float acc[4][VEC];
#pragma unroll
    for (int r = 0; r < 4; r++)
#pragma unroll
        for (int v = 0; v < VEC; v++) acc[r][v] = 0.f;

#pragma unroll
    for (int k = 0; k < K; k++) {
        float wv[VEC];
        if constexpr (VEC == 4) {
            float4 t = __ldg((const float4*)(W + (size_t)k * NC) + lane);
            wv[0] = t.x; wv[1] = t.y; wv[2] = t.z; wv[3] = t.w;
        } else {
            float2 t = __ldg((const float2*)(W + (size_t)k * NC) + lane);
            wv[0] = t.x; wv[1] = t.y;
        }
#pragma unroll
        for (int r = 0; r < 4; r++) {
            float xk = __shfl_sync(0xffffffffu, xr[r][k >> 5], k & 31);
#pragma unroll
            for (int v = 0; v < VEC; v++) acc[r][v] = fmaf(xk, wv[v], acc[r][v]);
        }
    }

#pragma unroll
    for (int r = 0; r < 4; r++) {
        int row = r0 + r;
        if (row < M) {
            float* yp = Y + (size_t)row * NC + lane * VEC;
#pragma unroll
            for (int v = 0; v < VEC; v++) yp[v] = acc[r][v];
        }
    }
}

// ---------------- attention logits, layer 1: warp per node, half-warp per head ----------------
__global__ void attn_logits1(const float* __restrict__ a_src, const float* __restrict__ a_dst) {
    int warp = (blockIdx.x * blockDim.x + threadIdx.x) >> 5;
    if (warp >= NNODE) return;
    int lane = threadIdx.x & 31;
    int head = lane >> 4, c0 = lane & 15;
    const float* hr = g_h1 + (size_t)warp * C1 + head * 64;
    float ps = 0.f, pd = 0.f;
#pragma unroll
    for (int j = 0; j < 4; j++) {
        int c = c0 + 16 * j;
        float hv = hr[c];
        ps = fmaf(hv, __ldg(a_src + head * 64 + c), ps);
        pd = fmaf(hv, __ldg(a_dst + head * 64 + c), pd);
    }
#pragma unroll
    for (int o = 8; o > 0; o >>= 1) {
        ps += __shfl_down_sync(0xffffffffu, ps, o);
        pd += __shfl_down_sync(0xffffffffu, pd, o);
    }
    if (c0 == 0) { g_als1[warp * 2 + head] = ps; g_ald1[warp * 2 + head] = pd; }
}

// ---------------- attention logits, layer 2: warp per node ----------------
__global__ void attn_logits2(const float* __restrict__ a_src, const float* __restrict__ a_dst) {
    int warp = (blockIdx.x * blockDim.x + threadIdx.x) >> 5;
    if (warp >= NNODE) return;
    int lane = threadIdx.x & 31;
    const float* hr = g_h3 + (size_t)warp * C2;
    float ps = 0.f, pd = 0.f;
#pragma unroll
    for (int j = 0; j < 2; j++) {
        int c = lane + 32 * j;
        float hv = hr[c];
        ps = fmaf(hv, __ldg(a_src + c), ps);
        pd = fmaf(hv, __ldg(a_dst + c), pd);
    }
#pragma unroll
    for (int o = 16; o > 0; o >>= 1) {
        ps += __shfl_xor_sync(0xffffffffu, ps, o);
        pd += __shfl_xor_sync(0xffffffffu, pd, o);
    }
    if (lane == 0) { g_als2[warp] = ps; g_ald2[warp] = pd; }
}

// ---------------- segment max over dst ----------------
__global__ void edge_max1(const int* __restrict__ ei, int E, int ETot) {
    int i = blockIdx.x * blockDim.x + threadIdx.x;
    if (i >= ETot) return;
    int s, d;
    if (i < E) { s = __ldg(ei + i); d = __ldg(ei + E + i); } else { s = d = i - E; }
#pragma unroll
    for (int h = 0; h < 2; h++) {
        float v = leaky(__ldg(&g_als1[s * 2 + h]) + __ldg(&g_ald1[d * 2 + h]));
        atomicMaxF(&g_m1[d * 2 + h], v);
    }
}

__global__ void edge_max2(const int* __restrict__ ei, int E, int ETot) {
    int i = blockIdx.x * blockDim.x + threadIdx.x;
    if (i >= ETot) return;
    int s, d;
    if (i < E) { s = __ldg(ei + i); d = __ldg(ei + E + i); } else { s = d = i - E; }
    float v = leaky(__ldg(&g_als2[s]) + __ldg(&g_ald2[d]));
    atomicMaxF(&g_m2[d], v);
}

// ---------------- fused exp + weighted scatter (unnormalized softmax) ----------------
// layer 1: one warp per edge; lane owns a float4 of the 128 channels; head = lane>>4.
__global__ void edge_agg1(const int* __restrict__ ei, int E, int ETot) {
    int gw = (blockIdx.x * blockDim.x + threadIdx.x) >> 5;
    if (gw >= ETot) return;
    int lane = threadIdx.x & 31;
    int s, d;
    if (gw < E) { s = __ldg(ei + gw); d = __ldg(ei + E + gw); } else { s = d = gw - E; }
    int head = lane >> 4;
    float e = leaky(__ldg(&g_als1[s * 2 + head]) + __ldg(&g_ald1[d * 2 + head]));
    float w = expf(e - __ldg(&g_m1[d * 2 + head]));   // <= 1, no overflow
    const float4 hv = *reinterpret_cast<const float4*>(g_h1 + (size_t)s * C1 + lane * 4);
    float4 v; v.x = hv.x * w; v.y = hv.y * w; v.z = hv.z * w; v.w = hv.w * w;
    float* dst = g_out1 + (size_t)d * C1 + lane * 4;
    asm volatile("red.global.add.v4.f32 [%0], {%1,%2,%3,%4};"
                 :: "l"(dst), "f"(v.x), "f"(v.y), "f"(v.z), "f"(v.w) : "memory");
    if ((lane & 15) == 0) atomicAdd(&g_z1[d * 2 + head], w);
}

// layer 2: half-warp per edge (16 lanes x float4 = 64 channels)
__global__ void edge_agg2(const int* __restrict__ ei, float* __restrict__ oacc, int E, int ETot) {
    int gw = (blockIdx.x * blockDim.x + threadIdx.x) >> 5;
    int lane = threadIdx.x & 31;
    int eidx = gw * 2 + (lane >> 4);
    if (eidx >= ETot) return;
    int l16 = lane & 15;
    int s, d;
    if (eidx < E) { s = __ldg(ei + eidx); d = __ldg(ei + E + eidx); } else { s = d = eidx - E; }
    float e = leaky(__ldg(&g_als2[s]) + __ldg(&g_ald2[d]));
    float w = expf(e - __ldg(&g_m2[d]));
    const float4 hv = *reinterpret_cast<const float4*>(g_h3 + (size_t)s * C2 + l16 * 4);
    float4 v; v.x = hv.x * w; v.y = hv.y * w; v.z = hv.z * w; v.w = hv.w * w;
    float* dst = oacc + (size_t)d * C2 + l16 * 4;
    asm volatile("red.global.add.v4.f32 [%0], {%1,%2,%3,%4};"
                 :: "l"(dst), "f"(v.x), "f"(v.y), "f"(v.z), "f"(v.w) : "memory");
    if (l16 == 0) atomicAdd(&g_z2[d], w);
}

// ---------------- normalize + bias + elu (layer 1), in place -> h2 ----------------
__global__ void norm_elu1(const float* __restrict__ b1) {
    int i = blockIdx.x * blockDim.x + threadIdx.x;
    if (i >= NNODE * C1) return;
    int n = i >> 7, j = i & 127, head = j >> 6;
    float v = g_out1[i] / g_z1[n * 2 + head] + __ldg(b1 + j);
    g_out1[i] = v > 0.f ? v : expm1f(v);
}

// ---------------- normalize + bias (layer 2, final output) ----------------
__global__ void finalize2(float* __restrict__ out, const float* __restrict__ b2) {
    int i = blockIdx.x * blockDim.x + threadIdx.x;
    if (i >= NNODE * C2) return;
    int n = i >> 6, c = i & 63;
    out[i] = out[i] / g_z2[n] + __ldg(b2 + c);
}

// ---------------- launch ----------------
extern "C" void kernel_launch(void* const* d_in, const int* in_sizes, int n_in,
                              void* d_out, int out_size) {
    const float* x      = (const float*)d_in[0];
    const int*   ei     = (const int*)  d_in[1];
    const float* W1     = (const float*)d_in[2];
    const float* a_src1 = (const float*)d_in[3];
    const float* a_dst1 = (const float*)d_in[4];
    const float* b1     = (const float*)d_in[5];
    const float* W2     = (const float*)d_in[6];
    const float* a_src2 = (const float*)d_in[7];
    const float* a_dst2 = (const float*)d_in[8];
    const float* b2     = (const float*)d_in[9];
    float* out = (float*)d_out;

    const int E = in_sizes[1] / 2;
    const int ETot = E + NNODE;
    const int TB = 256;

    // device-symbol addresses for the generic GEMM (host cannot take &g_arr directly)
    float *p_h1 = nullptr, *p_out1 = nullptr, *p_h3 = nullptr;
    cudaGetSymbolAddress((void**)&p_h1,  g_h1);
    cudaGetSymbolAddress((void**)&p_out1, g_out1);
    cudaGetSymbolAddress((void**)&p_h3,  g_h3);

    // 0) init
    init_kernel<<<(NNODE * C1 + TB - 1) / TB, TB>>>(out);

    // 1) layer 1 GEMM + logits
    {
        int warps = (NNODE + 3) / 4;
        gemm_rows<DIN, 4><<<(warps * 32 + TB - 1) / TB, TB>>>(x, W1, p_h1, NNODE);
    }
    attn_logits1<<<(NNODE * 32 + TB - 1) / TB, TB>>>(a_src1, a_dst1);

    // 2) layer 1 edge passes
    edge_max1<<<(ETot + TB - 1) / TB, TB>>>(ei, E, ETot);
    edge_agg1<<<((size_t)ETot * 32 + TB - 1) / TB, TB>>>(ei, E, ETot);

    // 3) normalize + bias + elu -> h2 (in g_out1)
    norm_elu1<<<(NNODE * C1 + TB - 1) / TB, TB>>>(b1);

    // 4) layer 2 GEMM + logits
    {
        int warps = (NNODE + 3) / 4;
        gemm_rows<C1, 2><<<(warps * 32 + TB - 1) / TB, TB>>>(p_out1, W2, p_h3, NNODE);
    }
    attn_logits2<<<(NNODE * 32 + TB - 1) / TB, TB>>>(a_src2, a_dst2);

    // 5) layer 2 edge passes (accumulate directly into d_out)
    edge_max2<<<(ETot + TB - 1) / TB, TB>>>(ei, E, ETot);
    {
        int warps = (ETot + 1) / 2;
        edge_agg2<<<((size_t)warps * 32 + TB - 1) / TB, TB>>>(ei, out, E, ETot);
    }

    // 6) final normalize + bias
    finalize2<<<(NNODE * C2 + TB - 1) / TB, TB>>>(out, b2);
}

// round 3
// speedup vs baseline: 1.5785x; 1.5785x over previous
#include <cuda_runtime.h>
#include <math.h>

#define NNODE 100000
#define DIN   256
#define C1    128   // H1*HID (2 heads x 64)
#define C2    64
#define MAXE  2200000

// ---------------- device scratch ----------------
static __device__ __align__(16) float g_h1[(size_t)NNODE * C1];  // x @ W1
static __device__ __align__(16) float g_h2[(size_t)NNODE * C1];  // after agg1+elu
static __device__ __align__(16) float g_h3[(size_t)NNODE * C2];  // h2 @ W2
static __device__ float g_als1[NNODE * 2];
static __device__ float g_ald1[NNODE * 2];
static __device__ float g_als2[NNODE];
static __device__ float g_ald2[NNODE];
static __device__ int g_deg [NNODE];
static __device__ int g_roff[NNODE];
static __device__ int g_cur [NNODE];
static __device__ int g_bsum[256];
static __device__ int g_csr [MAXE];

__device__ __forceinline__ float leaky(float v) { return v > 0.f ? v : 0.2f * v; }

// ---------------- CSR build ----------------
__global__ void zero_deg() {
    int i = blockIdx.x * blockDim.x + threadIdx.x;
    if (i < NNODE) g_deg[i] = 0;
}

__global__ void hist(const int* __restrict__ ei, int E, int ET) {
    int i = blockIdx.x * blockDim.x + threadIdx.x;
    if (i >= ET) return;
    int d = (i < E) ? __ldg(ei + E + i) : i - E;
    atomicAdd(&g_deg[d], 1);
}

// block-level exclusive scan (1024 threads/block)
__global__ void scanA() {
    int i = blockIdx.x * 1024 + threadIdx.x;
    int v = (i < NNODE) ? g_deg[i] : 0;
    int lane = threadIdx.x & 31, wid = threadIdx.x >> 5;
    int x = v;
#pragma unroll
    for (int o = 1; o < 32; o <<= 1) {
        int t = __shfl_up_sync(0xffffffffu, x, o);
        if (lane >= o) x += t;
    }
    __shared__ int ws[32];
    if (lane == 31) ws[wid] = x;
    __syncthreads();
    if (wid == 0) {
        int y = ws[lane];
#pragma unroll
        for (int o = 1; o < 32; o <<= 1) {
            int t = __shfl_up_sync(0xffffffffu, y, o);
            if (lane >= o) y += t;
        }
        ws[lane] = y;
    }
    __syncthreads();
    int excl = x - v + (wid > 0 ? ws[wid - 1] : 0);
    if (i < NNODE) g_roff[i] = excl;
    if (threadIdx.x == 0) g_bsum[blockIdx.x] = ws[31];
}

__global__ void scanB(int nb) {
    int t = threadIdx.x;              // 256 threads, nb <= 256
    int v = (t < nb) ? g_bsum[t] : 0;
    int lane = t & 31, wid = t >> 5;
    int x = v;
#pragma unroll
    for (int o = 1; o < 32; o <<= 1) {
        int u = __shfl_up_sync(0xffffffffu, x, o);
        if (lane >= o) x += u;
    }
    __shared__ int ws[8];
    if (lane == 31) ws[wid] = x;
    __syncthreads();
    int carry = 0;
    for (int k = 0; k < wid; k++) carry += ws[k];
    int excl = x - v + carry;
    if (t < nb) g_bsum[t] = excl;
}

__global__ void scanC() {
    int i = blockIdx.x * blockDim.x + threadIdx.x;
    if (i >= NNODE) return;
    int r = g_roff[i] + g_bsum[i >> 10];
    g_roff[i] = r;
    g_cur[i]  = r;
}

__global__ void scatter(const int* __restrict__ ei, int E, int ET) {
    int i = blockIdx.x * blockDim.x + threadIdx.x;
    if (i >= ET) return;
    int s, d;
    if (i < E) { s = __ldg(ei + i); d = __ldg(ei + E + i); } else { s = d = i - E; }
    int p = atomicAdd(&g_cur[d], 1);
    g_csr[p] = s;
}

// ---------------- GEMM1 fused with attention logits ----------------
// warp computes 4 rows x 128 cols; lane owns cols [lane*4, lane*4+4)
__global__ void __launch_bounds__(256) gemm1(const float* __restrict__ X,
                                             const float* __restrict__ W,
                                             const float* __restrict__ as,
                                             const float* __restrict__ ad) {
    int warp = (int)((blockIdx.x * blockDim.x + threadIdx.x) >> 5);
    int lane = threadIdx.x & 31;
    int r0 = warp * 4;
    if (r0 >= NNODE) return;

    float xr[4][DIN / 32];
#pragma unroll
    for (int r = 0; r < 4; r++) {
        const float* xp = X + (size_t)(r0 + r) * DIN;
#pragma unroll
        for (int i = 0; i < DIN / 32; i++) xr[r][i] = __ldg(xp + i * 32 + lane);
    }

    float acc[4][4];
#pragma unroll
    for (int r = 0; r < 4; r++)
#pragma unroll
        for (int v = 0; v < 4; v++) acc[r][v] = 0.f;

#pragma unroll
    for (int k = 0; k < DIN; k++) {
        float4 wv = __ldg((const float4*)(W + (size_t)k * C1) + lane);
#pragma unroll
        for (int r = 0; r < 4; r++) {
            float xk = __shfl_sync(0xffffffffu, xr[r][k >> 5], k & 31);
            acc[r][0] = fmaf(xk, wv.x, acc[r][0]);
            acc[r][1] = fmaf(xk, wv.y, acc[r][1]);
            acc[r][2] = fmaf(xk, wv.z, acc[r][2]);
            acc[r][3] = fmaf(xk, wv.w, acc[r][3]);
        }
    }

    // epilogue: store h row + per-head logit reduction
    float av[4], dv[4];
#pragma unroll
    for (int v = 0; v < 4; v++) {
        av[v] = __ldg(as + lane * 4 + v);
        dv[v] = __ldg(ad + lane * 4 + v);
    }
    int head = lane >> 4;
#pragma unroll
    for (int r = 0; r < 4; r++) {
        int row = r0 + r;
        *(float4*)(g_h1 + (size_t)row * C1 + lane * 4) =
            make_float4(acc[r][0], acc[r][1], acc[r][2], acc[r][3]);
        float sp = 0.f, dp = 0.f;
#pragma unroll
        for (int v = 0; v < 4; v++) {
            sp = fmaf(acc[r][v], av[v], sp);
            dp = fmaf(acc[r][v], dv[v], dp);
        }
#pragma unroll
        for (int o = 8; o > 0; o >>= 1) {
            sp += __shfl_xor_sync(0xffffffffu, sp, o);
            dp += __shfl_xor_sync(0xffffffffu, dp, o);
        }
        if ((lane & 15) == 0) {
            g_als1[row * 2 + head] = sp;
            g_ald1[row * 2 + head] = dp;
        }
    }
}

// ---------------- GEMM2 fused with logits (K=128, NC=64) ----------------
__global__ void __launch_bounds__(256) gemm2(const float* __restrict__ W,
                                             const float* __restrict__ as,
                                             const float* __restrict__ ad) {
    int warp = (int)((blockIdx.x * blockDim.x + threadIdx.x) >> 5);
    int lane = threadIdx.x & 31;
    int r0 = warp * 4;
    if (r0 >= NNODE) return;

    float xr[4][C1 / 32];
#pragma unroll
    for (int r = 0; r < 4; r++) {
        const float* xp = g_h2 + (size_t)(r0 + r) * C1;
#pragma unroll
        for (int i = 0; i < C1 / 32; i++) xr[r][i] = xp[i * 32 + lane];
    }

    float acc[4][2];
#pragma unroll
    for (int r = 0; r < 4; r++) { acc[r][0] = 0.f; acc[r][1] = 0.f; }

#pragma unroll
    for (int k = 0; k < C1; k++) {
        float2 wv = __ldg((const float2*)(W + (size_t)k * C2) + lane);
#pragma unroll
        for (int r = 0; r < 4; r++) {
            float xk = __shfl_sync(0xffffffffu, xr[r][k >> 5], k & 31);
            acc[r][0] = fmaf(xk, wv.x, acc[r][0]);
            acc[r][1] = fmaf(xk, wv.y, acc[r][1]);
        }
    }

    float a0 = __ldg(as + lane * 2), a1 = __ldg(as + lane * 2 + 1);
    float d0 = __ldg(ad + lane * 2), d1 = __ldg(ad + lane * 2 + 1);
#pragma unroll
    for (int r = 0; r < 4; r++) {
        int row = r0 + r;
        *(float2*)(g_h3 + (size_t)row * C2 + lane * 2) = make_float2(acc[r][0], acc[r][1]);
        float sp = fmaf(acc[r][1], a1, acc[r][0] * a0);
        float dp = fmaf(acc[r][1], d1, acc[r][0] * d0);
#pragma unroll
        for (int o = 16; o > 0; o >>= 1) {
            sp += __shfl_xor_sync(0xffffffffu, sp, o);
            dp += __shfl_xor_sync(0xffffffffu, dp, o);
        }
        if (lane == 0) { g_als2[row] = sp; g_ald2[row] = dp; }
    }
}

// ---------------- layer-1 aggregation: warp per dst node, gather-only ----------------
// software-pipelined: prefetch next neighbor index + logit while fma-ing current.
__global__ void __launch_bounds__(256) agg1(const float* __restrict__ b1) {
    int n = (int)((blockIdx.x * blockDim.x + threadIdx.x) >> 5);
    if (n >= NNODE) return;
    int lane = threadIdx.x & 31;
    int head = lane >> 4;
    int start = g_roff[n], len = g_deg[n];
    float aldv = __ldg(&g_ald1[n * 2 + head]);
    const int* cp = g_csr + start;

    float4 acc = make_float4(0.f, 0.f, 0.f, 0.f);
    float z = 0.f;

    int s_cur = __ldg(cp);                       // len >= 1 (self loop)
    float al_cur = __ldg(&g_als1[s_cur * 2 + head]);
    for (int j = 0; j < len; j++) {
        int s_nxt = 0; float al_nxt = 0.f;
        if (j + 1 < len) {
            s_nxt = __ldg(cp + j + 1);
            al_nxt = __ldg(&g_als1[s_nxt * 2 + head]);
        }
        float w = expf(leaky(al_cur + aldv));
        float4 hv = *(const float4*)(g_h1 + (size_t)s_cur * C1 + lane * 4);
        acc.x = fmaf(w, hv.x, acc.x);
        acc.y = fmaf(w, hv.y, acc.y);
        acc.z = fmaf(w, hv.z, acc.z);
        acc.w = fmaf(w, hv.w, acc.w);
        z += w;
        s_cur = s_nxt; al_cur = al_nxt;
    }
    float inv = 1.f / z;
    float4 bv = __ldg((const float4*)b1 + lane);
    float o0 = fmaf(acc.x, inv, bv.x);
    float o1 = fmaf(acc.y, inv, bv.y);
    float o2 = fmaf(acc.z, inv, bv.z);
    float o3 = fmaf(acc.w, inv, bv.w);
    o0 = o0 > 0.f ? o0 : expm1f(o0);
    o1 = o1 > 0.f ? o1 : expm1f(o1);
    o2 = o2 > 0.f ? o2 : expm1f(o2);
    o3 = o3 > 0.f ? o3 : expm1f(o3);
    *(float4*)(g_h2 + (size_t)n * C1 + lane * 4) = make_float4(o0, o1, o2, o3);
}

// ---------------- layer-2 aggregation: warp per node, 2 edges in flight ----------------
__global__ void __launch_bounds__(256) agg2(float* __restrict__ out,
                                            const float* __restrict__ b2) {
    int n = (int)((blockIdx.x * blockDim.x + threadIdx.x) >> 5);
    if (n >= NNODE) return;
    int lane = threadIdx.x & 31;
    int half = lane >> 4, l = lane & 15;
    int start = g_roff[n], len = g_deg[n];
    float aldv = __ldg(&g_ald2[n]);
    const int* cp = g_csr + start;

    float4 acc = make_float4(0.f, 0.f, 0.f, 0.f);
    float z = 0.f;

    int j = half;
    int s_cur = 0; float al_cur = 0.f;
    if (j < len) { s_cur = __ldg(cp + j); al_cur = __ldg(&g_als2[s_cur]); }
    for (; j < len; j += 2) {
        int s_nxt = 0; float al_nxt = 0.f;
        if (j + 2 < len) {
            s_nxt = __ldg(cp + j + 2);
            al_nxt = __ldg(&g_als2[s_nxt]);
        }
        float w = expf(leaky(al_cur + aldv));
        float4 hv = *(const float4*)(g_h3 + (size_t)s_cur * C2 + l * 4);
        acc.x = fmaf(w, hv.x, acc.x);
        acc.y = fmaf(w, hv.y, acc.y);
        acc.z = fmaf(w, hv.z, acc.z);
        acc.w = fmaf(w, hv.w, acc.w);
        z += w;
        s_cur = s_nxt; al_cur = al_nxt;
    }
    acc.x += __shfl_xor_sync(0xffffffffu, acc.x, 16);
    acc.y += __shfl_xor_sync(0xffffffffu, acc.y, 16);
    acc.z += __shfl_xor_sync(0xffffffffu, acc.z, 16);
    acc.w += __shfl_xor_sync(0xffffffffu, acc.w, 16);
    z     += __shfl_xor_sync(0xffffffffu, z, 16);
    if (half == 0) {
        float inv = 1.f / z;
        float4 bv = __ldg((const float4*)b2 + l);
        *(float4*)(out + (size_t)n * C2 + l * 4) =
            make_float4(fmaf(acc.x, inv, bv.x), fmaf(acc.y, inv, bv.y),
                        fmaf(acc.z, inv, bv.z), fmaf(acc.w, inv, bv.w));
    }
}

// ---------------- launch ----------------
extern "C" void kernel_launch(void* const* d_in, const int* in_sizes, int n_in,
                              void* d_out, int out_size) {
    const float* x      = (const float*)d_in[0];
    const int*   ei     = (const int*)  d_in[1];
    const float* W1     = (const float*)d_in[2];
    const float* a_src1 = (const float*)d_in[3];
    const float* a_dst1 = (const float*)d_in[4];
    const float* b1     = (const float*)d_in[5];
    const float* W2     = (const float*)d_in[6];
    const float* a_src2 = (const float*)d_in[7];
    const float* a_dst2 = (const float*)d_in[8];
    const float* b2     = (const float*)d_in[9];
    float* out = (float*)d_out;

    const int E = in_sizes[1] / 2;
    const int ET = E + NNODE;
    const int TB = 256;
    const int nbScan = (NNODE + 1023) / 1024;

    // CSR build (layer-independent)
    zero_deg<<<(NNODE + TB - 1) / TB, TB>>>();
    hist<<<(ET + TB - 1) / TB, TB>>>(ei, E, ET);
    scanA<<<nbScan, 1024>>>();
    scanB<<<1, 256>>>(nbScan);
    scanC<<<(NNODE + TB - 1) / TB, TB>>>();
    scatter<<<(ET + TB - 1) / TB, TB>>>(ei, E, ET);

    // layer 1
    gemm1<<<(NNODE / 4 * 32 + TB - 1) / TB, TB>>>(x, W1, a_src1, a_dst1);
    agg1<<<(NNODE * 32 + TB - 1) / TB, TB>>>(b1);

    // layer 2
    gemm2<<<(NNODE / 4 * 32 + TB - 1) / TB, TB>>>(W2, a_src2, a_dst2);
    agg2<<<(NNODE * 32 + TB - 1) / TB, TB>>>(out, b2);
}

// round 5
// speedup vs baseline: 2.0126x; 1.2750x over previous
#include <cuda_runtime.h>
#include <cuda_bf16.h>
#include <math.h>
#include <stdint.h>

#define NNODE 100000
#define DIN   256
#define C1    128   // H1*HID (2 heads x 64)
#define C2    64
#define MAXE  2200000

// ---------------- device scratch ----------------
static __device__ __align__(16) float g_h1[(size_t)NNODE * C1];  // x @ W1
static __device__ __align__(16) float g_h2[(size_t)NNODE * C1];  // after agg1+elu
static __device__ __align__(16) float g_h3[(size_t)NNODE * C2];  // h2 @ W2
static __device__ float g_als1[NNODE * 2];
static __device__ float g_ald1[NNODE * 2];
static __device__ float g_als2[NNODE];
static __device__ float g_ald2[NNODE];
static __device__ int g_deg [NNODE];
static __device__ int g_roff[NNODE];
static __device__ int g_cur [NNODE];
static __device__ int g_bsum[256];
static __device__ int g_csr [MAXE];

__device__ __forceinline__ float leaky(float v) { return v > 0.f ? v : 0.2f * v; }

__device__ __forceinline__ uint32_t smem_u32(const void* p) {
    uint32_t a;
    asm("{ .reg .u64 t; cvta.to.shared.u64 t, %1; cvt.u32.u64 %0, t; }" : "=r"(a) : "l"(p));
    return a;
}

__device__ __forceinline__ uint32_t pack_bf16(float a, float b) {
    return (uint32_t)__bfloat16_as_ushort(__float2bfloat16(a)) |
           ((uint32_t)__bfloat16_as_ushort(__float2bfloat16(b)) << 16);
}

__device__ __forceinline__ void mma16816(float* d, const uint32_t* a, uint32_t b0, uint32_t b1) {
    asm volatile(
        "mma.sync.aligned.m16n8k16.row.col.f32.bf16.bf16.f32 "
        "{%0,%1,%2,%3}, {%4,%5,%6,%7}, {%8,%9}, {%0,%1,%2,%3};"
        : "+f"(d[0]), "+f"(d[1]), "+f"(d[2]), "+f"(d[3])
        : "r"(a[0]), "r"(a[1]), "r"(a[2]), "r"(a[3]), "r"(b0), "r"(b1));
}

// ---------------- GEMM1: split-bf16 tensor-core (mma.sync) + fused logits ----------------
// CTA: 256 thr (8 warps). Tile 128 rows x 128 cols, K=256 in 4 chunks of 64.
// SMEM: sA hi/lo 128x72 bf16 (stride 144B), sB hi/lo 64x136 bf16 (stride 272B).
#define SA_STRIDE 72      // bf16 units
#define SB_STRIDE 136
#define SA_BYTES  (128 * SA_STRIDE * 2)     // 18432 per part
#define SB_BYTES  (64 * SB_STRIDE * 2)      // 17408 per part
#define SM_A_HI   0
#define SM_A_LO   SA_BYTES
#define SM_B_HI   (2 * SA_BYTES)
#define SM_B_LO   (2 * SA_BYTES + SB_BYTES)
#define G1_SMEM   (2 * SA_BYTES + 2 * SB_BYTES)   // 71680

__global__ void __launch_bounds__(256) gemm1_mma(
        const float* __restrict__ X, const float* __restrict__ W,
        const float* __restrict__ as, const float* __restrict__ ad) {
    extern __shared__ char smem[];
    uint32_t sb = smem_u32(smem);
    int tid = threadIdx.x;
    int w = tid >> 5, lane = tid & 31;
    int g = lane >> 2, tg = lane & 3;
    int blk = blockIdx.x;

    float acc[16][4];
#pragma unroll
    for (int nt = 0; nt < 16; nt++)
#pragma unroll
        for (int q = 0; q < 4; q++) acc[nt][q] = 0.f;

    uint32_t* sAhi = (uint32_t*)(smem + SM_A_HI);
    uint32_t* sAlo = (uint32_t*)(smem + SM_A_LO);
    uint32_t* sBhi = (uint32_t*)(smem + SM_B_HI);
    uint32_t* sBlo = (uint32_t*)(smem + SM_B_LO);

    for (int kc = 0; kc < 4; kc++) {
        // ---- stage A chunk: rows 0..127 of this block, k in [kc*64, kc*64+64) ----
        for (int i = tid; i < 128 * 16; i += 256) {
            int row = i >> 4, q = i & 15;
            int rg = blk * 128 + row; if (rg >= NNODE) rg = NNODE - 1;
            float4 v = __ldg((const float4*)(X + (size_t)rg * DIN + kc * 64) + q);
            float h0 = __bfloat162float(__float2bfloat16(v.x));
            float h1 = __bfloat162float(__float2bfloat16(v.y));
            float h2 = __bfloat162float(__float2bfloat16(v.z));
            float h3 = __bfloat162float(__float2bfloat16(v.w));
            int o = row * (SA_STRIDE / 2) + q * 2;
            sAhi[o]     = pack_bf16(v.x, v.y);
            sAhi[o + 1] = pack_bf16(v.z, v.w);
            sAlo[o]     = pack_bf16(v.x - h0, v.y - h1);
            sAlo[o + 1] = pack_bf16(v.z - h2, v.w - h3);
        }
        // ---- stage B chunk: W[k][0..127], k in chunk ----
        for (int i = tid; i < 64 * 32; i += 256) {
            int kk = i >> 5, q = i & 31;
            float4 v = __ldg((const float4*)(W + (size_t)(kc * 64 + kk) * C1) + q);
            float h0 = __bfloat162float(__float2bfloat16(v.x));
            float h1 = __bfloat162float(__float2bfloat16(v.y));
            float h2 = __bfloat162float(__float2bfloat16(v.z));
            float h3 = __bfloat162float(__float2bfloat16(v.w));
            int o = kk * (SB_STRIDE / 2) + q * 2;
            sBhi[o]     = pack_bf16(v.x, v.y);
            sBhi[o + 1] = pack_bf16(v.z, v.w);
            sBlo[o]     = pack_bf16(v.x - h0, v.y - h1);
            sBlo[o + 1] = pack_bf16(v.z - h2, v.w - h3);
        }
        __syncthreads();

        // ---- compute: 4 k16 sub-chunks ----
#pragma unroll
        for (int sub = 0; sub < 4; sub++) {
            int kbase = sub * 16;
            // A fragment addresses: lanes 0-15 -> rows 0-15 @k+0; 16-31 -> rows @k+8
            int ar = w * 16 + (lane & 15);
            int ak = kbase + ((lane >> 4) << 3);
            uint32_t aoff = (uint32_t)(ar * SA_STRIDE + ak) * 2;
            uint32_t ahi[4], alo[4];
            asm volatile("ldmatrix.sync.aligned.m8n8.x4.shared.b16 {%0,%1,%2,%3}, [%4];"
                : "=r"(ahi[0]), "=r"(ahi[1]), "=r"(ahi[2]), "=r"(ahi[3])
                : "r"(sb + SM_A_HI + aoff));
            asm volatile("ldmatrix.sync.aligned.m8n8.x4.shared.b16 {%0,%1,%2,%3}, [%4];"
                : "=r"(alo[0]), "=r"(alo[1]), "=r"(alo[2]), "=r"(alo[3])
                : "r"(sb + SM_A_LO + aoff));
#pragma unroll
            for (int nt = 0; nt < 16; nt++) {
                uint32_t boff = (uint32_t)((kbase + (lane & 15)) * SB_STRIDE + nt * 8) * 2;
                uint32_t bh0, bh1, bl0, bl1;
                asm volatile("ldmatrix.sync.aligned.m8n8.x2.trans.shared.b16 {%0,%1}, [%2];"
                    : "=r"(bh0), "=r"(bh1) : "r"(sb + SM_B_HI + boff));
                asm volatile("ldmatrix.sync.aligned.m8n8.x2.trans.shared.b16 {%0,%1}, [%2];"
                    : "=r"(bl0), "=r"(bl1) : "r"(sb + SM_B_LO + boff));
                mma16816(acc[nt], ahi, bh0, bh1);
                mma16816(acc[nt], ahi, bl0, bl1);
                mma16816(acc[nt], alo, bh0, bh1);
            }
        }
        __syncthreads();
    }

    // ---- epilogue: store h1 + fused logits ----
    int rowA = blk * 128 + w * 16 + g;      // rows rowA and rowA+8
    float sp[2][2] = {{0.f, 0.f}, {0.f, 0.f}};
    float dp[2][2] = {{0.f, 0.f}, {0.f, 0.f}};
#pragma unroll
    for (int nt = 0; nt < 16; nt++) {
        int c0 = nt * 8 + tg * 2;
        int head = nt >> 3;
        float a0 = __ldg(as + c0), a1 = __ldg(as + c0 + 1);
        float d0 = __ldg(ad + c0), d1 = __ldg(ad + c0 + 1);
        sp[0][head] += acc[nt][0] * a0 + acc[nt][1] * a1;
        dp[0][head] += acc[nt][0] * d0 + acc[nt][1] * d1;
        sp[1][head] += acc[nt][2] * a0 + acc[nt][3] * a1;
        dp[1][head] += acc[nt][2] * d0 + acc[nt][3] * d1;
        if (rowA < NNODE)
            *(float2*)(g_h1 + (size_t)rowA * C1 + c0) = make_float2(acc[nt][0], acc[nt][1]);
        if (rowA + 8 < NNODE)
            *(float2*)(g_h1 + (size_t)(rowA + 8) * C1 + c0) = make_float2(acc[nt][2], acc[nt][3]);
    }
#pragma unroll
    for (int rh = 0; rh < 2; rh++)
#pragma unroll
        for (int hd = 0; hd < 2; hd++) {
            sp[rh][hd] += __shfl_xor_sync(0xffffffffu, sp[rh][hd], 1);
            sp[rh][hd] += __shfl_xor_sync(0xffffffffu, sp[rh][hd], 2);
            dp[rh][hd] += __shfl_xor_sync(0xffffffffu, dp[rh][hd], 1);
            dp[rh][hd] += __shfl_xor_sync(0xffffffffu, dp[rh][hd], 2);
        }
    if (tg == 0) {
#pragma unroll
        for (int rh = 0; rh < 2; rh++) {
            int row = rowA + rh * 8;
            if (row < NNODE) {
                g_als1[row * 2]     = sp[rh][0];  g_ald1[row * 2]     = dp[rh][0];
                g_als1[row * 2 + 1] = sp[rh][1];  g_ald1[row * 2 + 1] = dp[rh][1];
            }
        }
    }
}

// ---------------- CSR build ----------------
__global__ void zero_deg() {
    int i = blockIdx.x * blockDim.x + threadIdx.x;
    if (i < NNODE) g_deg[i] = 0;
}

__global__ void hist(const int* __restrict__ ei, int E, int ET) {
    int i = blockIdx.x * blockDim.x + threadIdx.x;
    if (i >= ET) return;
    int d = (i < E) ? __ldg(ei + E + i) : i - E;
    atomicAdd(&g_deg[d], 1);
}

__global__ void scanA() {
    int i = blockIdx.x * 1024 + threadIdx.x;
    int v = (i < NNODE) ? g_deg[i] : 0;
    int lane = threadIdx.x & 31, wid = threadIdx.x >> 5;
    int x = v;
#pragma unroll
    for (int o = 1; o < 32; o <<= 1) {
        int t = __shfl_up_sync(0xffffffffu, x, o);
        if (lane >= o) x += t;
    }
    __shared__ int ws[32];
    if (lane == 31) ws[wid] = x;
    __syncthreads();
    if (wid == 0) {
        int y = ws[lane];
#pragma unroll
        for (int o = 1; o < 32; o <<= 1) {
            int t = __shfl_up_sync(0xffffffffu, y, o);
            if (lane >= o) y += t;
        }
        ws[lane] = y;
    }
    __syncthreads();
    int excl = x - v + (wid > 0 ? ws[wid - 1] : 0);
    if (i < NNODE) g_roff[i] = excl;
    if (threadIdx.x == 0) g_bsum[blockIdx.x] = ws[31];
}

__global__ void scanB(int nb) {
    int t = threadIdx.x;
    int v = (t < nb) ? g_bsum[t] : 0;
    int lane = t & 31, wid = t >> 5;
    int x = v;
#pragma unroll
    for (int o = 1; o < 32; o <<= 1) {
        int u = __shfl_up_sync(0xffffffffu, x, o);
        if (lane >= o) x += u;
    }
    __shared__ int ws[8];
    if (lane == 31) ws[wid] = x;
    __syncthreads();
    int carry = 0;
    for (int k = 0; k < wid; k++) carry += ws[k];
    int excl = x - v + carry;
    if (t < nb) g_bsum[t] = excl;
}

__global__ void scanC() {
    int i = blockIdx.x * blockDim.x + threadIdx.x;
    if (i >= NNODE) return;
    int r = g_roff[i] + g_bsum[i >> 10];
    g_roff[i] = r;
    g_cur[i]  = r;
}

__global__ void scatter(const int* __restrict__ ei, int E, int ET) {
    int i = blockIdx.x * blockDim.x + threadIdx.x;
    if (i >= ET) return;
    int s, d;
    if (i < E) { s = __ldg(ei + i); d = __ldg(ei + E + i); } else { s = d = i - E; }
    int p = atomicAdd(&g_cur[d], 1);
    g_csr[p] = s;
}

// ---------------- GEMM2 fused with logits (K=128, NC=64), SIMT ----------------
__global__ void __launch_bounds__(256) gemm2(const float* __restrict__ W,
                                             const float* __restrict__ as,
                                             const float* __restrict__ ad) {
    int warp = (int)((blockIdx.x * blockDim.x + threadIdx.x) >> 5);
    int lane = threadIdx.x & 31;
    int r0 = warp * 4;
    if (r0 >= NNODE) return;

    float xr[4][C1 / 32];
#pragma unroll
    for (int r = 0; r < 4; r++) {
        const float* xp = g_h2 + (size_t)(r0 + r) * C1;
#pragma unroll
        for (int i = 0; i < C1 / 32; i++) xr[r][i] = xp[i * 32 + lane];
    }

    float acc[4][2];
#pragma unroll
    for (int r = 0; r < 4; r++) { acc[r][0] = 0.f; acc[r][1] = 0.f; }

#pragma unroll
    for (int k = 0; k < C1; k++) {
        float2 wv = __ldg((const float2*)(W + (size_t)k * C2) + lane);
#pragma unroll
        for (int r = 0; r < 4; r++) {
            float xk = __shfl_sync(0xffffffffu, xr[r][k >> 5], k & 31);
            acc[r][0] = fmaf(xk, wv.x, acc[r][0]);
            acc[r][1] = fmaf(xk, wv.y, acc[r][1]);
        }
    }

    float a0 = __ldg(as + lane * 2), a1 = __ldg(as + lane * 2 + 1);
    float d0 = __ldg(ad + lane * 2), d1 = __ldg(ad + lane * 2 + 1);
#pragma unroll
    for (int r = 0; r < 4; r++) {
        int row = r0 + r;
        *(float2*)(g_h3 + (size_t)row * C2 + lane * 2) = make_float2(acc[r][0], acc[r][1]);
        float sp = fmaf(acc[r][1], a1, acc[r][0] * a0);
        float dp = fmaf(acc[r][1], d1, acc[r][0] * d0);
#pragma unroll
        for (int o = 16; o > 0; o >>= 1) {
            sp += __shfl_xor_sync(0xffffffffu, sp, o);
            dp += __shfl_xor_sync(0xffffffffu, dp, o);
        }
        if (lane == 0) { g_als2[row] = sp; g_ald2[row] = dp; }
    }
}

// ---------------- layer-1 aggregation ----------------
__global__ void __launch_bounds__(256) agg1(const float* __restrict__ b1) {
    int n = (int)((blockIdx.x * blockDim.x + threadIdx.x) >> 5);
    if (n >= NNODE) return;
    int lane = threadIdx.x & 31;
    int head = lane >> 4;
    int start = g_roff[n], len = g_deg[n];
    float aldv = __ldg(&g_ald1[n * 2 + head]);
    const int* cp = g_csr + start;

    float4 acc = make_float4(0.f, 0.f, 0.f, 0.f);
    float z = 0.f;

    int s_cur = __ldg(cp);
    float al_cur = __ldg(&g_als1[s_cur * 2 + head]);
    for (int j = 0; j < len; j++) {
        int s_nxt = 0; float al_nxt = 0.f;
        if (j + 1 < len) {
            s_nxt = __ldg(cp + j + 1);
            al_nxt = __ldg(&g_als1[s_nxt * 2 + head]);
        }
        float w = expf(leaky(al_cur + aldv));
        float4 hv = *(const float4*)(g_h1 + (size_t)s_cur * C1 + lane * 4);
        acc.x = fmaf(w, hv.x, acc.x);
        acc.y = fmaf(w, hv.y, acc.y);
        acc.z = fmaf(w, hv.z, acc.z);
        acc.w = fmaf(w, hv.w, acc.w);
        z += w;
        s_cur = s_nxt; al_cur = al_nxt;
    }
    float inv = 1.f / z;
    float4 bv = __ldg((const float4*)b1 + lane);
    float o0 = fmaf(acc.x, inv, bv.x);
    float o1 = fmaf(acc.y, inv, bv.y);
    float o2 = fmaf(acc.z, inv, bv.z);
    float o3 = fmaf(acc.w, inv, bv.w);
    o0 = o0 > 0.f ? o0 : expm1f(o0);
    o1 = o1 > 0.f ? o1 : expm1f(o1);
    o2 = o2 > 0.f ? o2 : expm1f(o2);
    o3 = o3 > 0.f ? o3 : expm1f(o3);
    *(float4*)(g_h2 + (size_t)n * C1 + lane * 4) = make_float4(o0, o1, o2, o3);
}

// ---------------- layer-2 aggregation ----------------
__global__ void __launch_bounds__(256) agg2(float* __restrict__ out,
                                            const float* __restrict__ b2) {
    int n = (int)((blockIdx.x * blockDim.x + threadIdx.x) >> 5);
    if (n >= NNODE) return;
    int lane = threadIdx.x & 31;
    int half = lane >> 4, l = lane & 15;
    int start = g_roff[n], len = g_deg[n];
    float aldv = __ldg(&g_ald2[n]);
    const int* cp = g_csr + start;

    float4 acc = make_float4(0.f, 0.f, 0.f, 0.f);
    float z = 0.f;

    int j = half;
    int s_cur = 0; float al_cur = 0.f;
    if (j < len) { s_cur = __ldg(cp + j); al_cur = __ldg(&g_als2[s_cur]); }
    for (; j < len; j += 2) {
        int s_nxt = 0; float al_nxt = 0.f;
        if (j + 2 < len) {
            s_nxt = __ldg(cp + j + 2);
            al_nxt = __ldg(&g_als2[s_nxt]);
        }
        float w = expf(leaky(al_cur + aldv));
        float4 hv = *(const float4*)(g_h3 + (size_t)s_cur * C2 + l * 4);
        acc.x = fmaf(w, hv.x, acc.x);
        acc.y = fmaf(w, hv.y, acc.y);
        acc.z = fmaf(w, hv.z, acc.z);
        acc.w = fmaf(w, hv.w, acc.w);
        z += w;
        s_cur = s_nxt; al_cur = al_nxt;
    }
    acc.x += __shfl_xor_sync(0xffffffffu, acc.x, 16);
    acc.y += __shfl_xor_sync(0xffffffffu, acc.y, 16);
    acc.z += __shfl_xor_sync(0xffffffffu, acc.z, 16);
    acc.w += __shfl_xor_sync(0xffffffffu, acc.w, 16);
    z     += __shfl_xor_sync(0xffffffffu, z, 16);
    if (half == 0) {
        float inv = 1.f / z;
        float4 bv = __ldg((const float4*)b2 + l);
        *(float4*)(out + (size_t)n * C2 + l * 4) =
            make_float4(fmaf(acc.x, inv, bv.x), fmaf(acc.y, inv, bv.y),
                        fmaf(acc.z, inv, bv.z), fmaf(acc.w, inv, bv.w));
    }
}

// ---------------- launch ----------------
extern "C" void kernel_launch(void* const* d_in, const int* in_sizes, int n_in,
                              void* d_out, int out_size) {
    const float* x      = (const float*)d_in[0];
    const int*   ei     = (const int*)  d_in[1];
    const float* W1     = (const float*)d_in[2];
    const float* a_src1 = (const float*)d_in[3];
    const float* a_dst1 = (const float*)d_in[4];
    const float* b1     = (const float*)d_in[5];
    const float* W2     = (const float*)d_in[6];
    const float* a_src2 = (const float*)d_in[7];
    const float* a_dst2 = (const float*)d_in[8];
    const float* b2     = (const float*)d_in[9];
    float* out = (float*)d_out;

    const int E = in_sizes[1] / 2;
    const int ET = E + NNODE;
    const int TB = 256;
    const int nbScan = (NNODE + 1023) / 1024;

    cudaFuncSetAttribute(gemm1_mma, cudaFuncAttributeMaxDynamicSharedMemorySize, G1_SMEM);

    // CSR build (independent of features)
    zero_deg<<<(NNODE + TB - 1) / TB, TB>>>();
    hist<<<(ET + TB - 1) / TB, TB>>>(ei, E, ET);
    scanA<<<nbScan, 1024>>>();
    scanB<<<1, 256>>>(nbScan);
    scanC<<<(NNODE + TB - 1) / TB, TB>>>();
    scatter<<<(ET + TB - 1) / TB, TB>>>(ei, E, ET);

    // layer 1: tensor-core GEMM (+ fused logits), then gather-aggregate
    gemm1_mma<<<(NNODE + 127) / 128, 256, G1_SMEM>>>(x, W1, a_src1, a_dst1);
    agg1<<<(NNODE * 32 + TB - 1) / TB, TB>>>(b1);

    // layer 2
    gemm2<<<(NNODE / 4 * 32 + TB - 1) / TB, TB>>>(W2, a_src2, a_dst2);
    agg2<<<(NNODE * 32 + TB - 1) / TB, TB>>>(out, b2);
}

// round 7
// speedup vs baseline: 2.3750x; 1.1801x over previous
#include <cuda_runtime.h>
#include <cuda_bf16.h>
#include <cuda_fp16.h>
#include <math.h>
#include <stdint.h>

#define NNODE 100000
#define DIN   256
#define C1    128   // H1*HID (2 heads x 64)
#define C2    64
#define MAXE  2200000

// ---------------- device scratch ----------------
static __device__ __align__(16) __half g_h1[(size_t)NNODE * C1];  // x @ W1 (fp16)
static __device__ __align__(16) float  g_h2[(size_t)NNODE * C1];  // after agg1+elu (fp32)
static __device__ __align__(16) __half g_h3[(size_t)NNODE * C2];  // h2 @ W2 (fp16)
static __device__ float g_als1[NNODE * 2];
static __device__ float g_ald1[NNODE * 2];
static __device__ float g_als2[NNODE];
static __device__ float g_ald2[NNODE];
static __device__ int g_deg [NNODE];
static __device__ int g_roff[NNODE];
static __device__ int g_cur [NNODE];
static __device__ int g_bsum[256];
static __device__ int g_csr [MAXE];

__device__ __forceinline__ float leaky(float v) { return v > 0.f ? v : 0.2f * v; }

__device__ __forceinline__ uint32_t smem_u32(const void* p) {
    uint32_t a;
    asm("{ .reg .u64 t; cvta.to.shared.u64 t, %1; cvt.u32.u64 %0, t; }" : "=r"(a) : "l"(p));
    return a;
}

__device__ __forceinline__ uint32_t pack_bf16(float a, float b) {
    return (uint32_t)__bfloat16_as_ushort(__float2bfloat16(a)) |
           ((uint32_t)__bfloat16_as_ushort(__float2bfloat16(b)) << 16);
}

__device__ __forceinline__ void mma16816(float* d, const uint32_t* a, uint32_t b0, uint32_t b1) {
    asm volatile(
        "mma.sync.aligned.m16n8k16.row.col.f32.bf16.bf16.f32 "
        "{%0,%1,%2,%3}, {%4,%5,%6,%7}, {%8,%9}, {%0,%1,%2,%3};"
        : "+f"(d[0]), "+f"(d[1]), "+f"(d[2]), "+f"(d[3])
        : "r"(a[0]), "r"(a[1]), "r"(a[2]), "r"(a[3]), "r"(b0), "r"(b1));
}

// ================= GEMM1: split-bf16 mma.sync + fused logits =================
// CTA: 256 thr (8 warps). Tile 128 rows x 128 cols, K=256 in 4 chunks of 64.
#define SA_STRIDE 72      // bf16 units
#define SB_STRIDE 136
#define SA_BYTES  (128 * SA_STRIDE * 2)
#define SB_BYTES  (64 * SB_STRIDE * 2)
#define SM_A_HI   0
#define SM_A_LO   SA_BYTES
#define SM_B_HI   (2 * SA_BYTES)
#define SM_B_LO   (2 * SA_BYTES + SB_BYTES)
#define G1_SMEM   (2 * SA_BYTES + 2 * SB_BYTES)   // 71680

__global__ void __launch_bounds__(256) gemm1_mma(
        const float* __restrict__ X, const float* __restrict__ W,
        const float* __restrict__ as, const float* __restrict__ ad) {
    extern __shared__ char smem[];
    uint32_t sb = smem_u32(smem);
    int tid = threadIdx.x;
    int w = tid >> 5, lane = tid & 31;
    int g = lane >> 2, tg = lane & 3;
    int blk = blockIdx.x;

    float acc[16][4];
#pragma unroll
    for (int nt = 0; nt < 16; nt++)
#pragma unroll
        for (int q = 0; q < 4; q++) acc[nt][q] = 0.f;

    uint32_t* sAhi = (uint32_t*)(smem + SM_A_HI);
    uint32_t* sAlo = (uint32_t*)(smem + SM_A_LO);
    uint32_t* sBhi = (uint32_t*)(smem + SM_B_HI);
    uint32_t* sBlo = (uint32_t*)(smem + SM_B_LO);

    for (int kc = 0; kc < 4; kc++) {
        for (int i = tid; i < 128 * 16; i += 256) {
            int row = i >> 4, q = i & 15;
            int rg = blk * 128 + row; if (rg >= NNODE) rg = NNODE - 1;
            float4 v = __ldg((const float4*)(X + (size_t)rg * DIN + kc * 64) + q);
            float h0 = __bfloat162float(__float2bfloat16(v.x));
            float h1 = __bfloat162float(__float2bfloat16(v.y));
            float h2 = __bfloat162float(__float2bfloat16(v.z));
            float h3 = __bfloat162float(__float2bfloat16(v.w));
            int o = row * (SA_STRIDE / 2) + q * 2;
            sAhi[o]     = pack_bf16(v.x, v.y);
            sAhi[o + 1] = pack_bf16(v.z, v.w);
            sAlo[o]     = pack_bf16(v.x - h0, v.y - h1);
            sAlo[o + 1] = pack_bf16(v.z - h2, v.w - h3);
        }
        for (int i = tid; i < 64 * 32; i += 256) {
            int kk = i >> 5, q = i & 31;
            float4 v = __ldg((const float4*)(W + (size_t)(kc * 64 + kk) * C1) + q);
            float h0 = __bfloat162float(__float2bfloat16(v.x));
            float h1 = __bfloat162float(__float2bfloat16(v.y));
            float h2 = __bfloat162float(__float2bfloat16(v.z));
            float h3 = __bfloat162float(__float2bfloat16(v.w));
            int o = kk * (SB_STRIDE / 2) + q * 2;
            sBhi[o]     = pack_bf16(v.x, v.y);
            sBhi[o + 1] = pack_bf16(v.z, v.w);
            sBlo[o]     = pack_bf16(v.x - h0, v.y - h1);
            sBlo[o + 1] = pack_bf16(v.z - h2, v.w - h3);
        }
        __syncthreads();

#pragma unroll
        for (int sub = 0; sub < 4; sub++) {
            int kbase = sub * 16;
            int ar = w * 16 + (lane & 15);
            int ak = kbase + ((lane >> 4) << 3);
            uint32_t aoff = (uint32_t)(ar * SA_STRIDE + ak) * 2;
            uint32_t ahi[4], alo[4];
            asm volatile("ldmatrix.sync.aligned.m8n8.x4.shared.b16 {%0,%1,%2,%3}, [%4];"
                : "=r"(ahi[0]), "=r"(ahi[1]), "=r"(ahi[2]), "=r"(ahi[3])
                : "r"(sb + SM_A_HI + aoff));
            asm volatile("ldmatrix.sync.aligned.m8n8.x4.shared.b16 {%0,%1,%2,%3}, [%4];"
                : "=r"(alo[0]), "=r"(alo[1]), "=r"(alo[2]), "=r"(alo[3])
                : "r"(sb + SM_A_LO + aoff));
#pragma unroll
            for (int nt = 0; nt < 16; nt++) {
                uint32_t boff = (uint32_t)((kbase + (lane & 15)) * SB_STRIDE + nt * 8) * 2;
                uint32_t bh0, bh1, bl0, bl1;
                asm volatile("ldmatrix.sync.aligned.m8n8.x2.trans.shared.b16 {%0,%1}, [%2];"
                    : "=r"(bh0), "=r"(bh1) : "r"(sb + SM_B_HI + boff));
                asm volatile("ldmatrix.sync.aligned.m8n8.x2.trans.shared.b16 {%0,%1}, [%2];"
                    : "=r"(bl0), "=r"(bl1) : "r"(sb + SM_B_LO + boff));
                mma16816(acc[nt], ahi, bh0, bh1);
                mma16816(acc[nt], ahi, bl0, bl1);
                mma16816(acc[nt], alo, bh0, bh1);
            }
        }
        __syncthreads();
    }

    // ---- epilogue: store h1 (fp16) + fused logits ----
    int rowA = blk * 128 + w * 16 + g;
    float sp[2][2] = {{0.f, 0.f}, {0.f, 0.f}};
    float dp[2][2] = {{0.f, 0.f}, {0.f, 0.f}};
#pragma unroll
    for (int nt = 0; nt < 16; nt++) {
        int c0 = nt * 8 + tg * 2;
        int head = nt >> 3;
        float a0 = __ldg(as + c0), a1 = __ldg(as + c0 + 1);
        float d0 = __ldg(ad + c0), d1 = __ldg(ad + c0 + 1);
        sp[0][head] += acc[nt][0] * a0 + acc[nt][1] * a1;
        dp[0][head] += acc[nt][0] * d0 + acc[nt][1] * d1;
        sp[1][head] += acc[nt][2] * a0 + acc[nt][3] * a1;
        dp[1][head] += acc[nt][2] * d0 + acc[nt][3] * d1;
        if (rowA < NNODE)
            *(__half2*)(g_h1 + (size_t)rowA * C1 + c0) = __floats2half2_rn(acc[nt][0], acc[nt][1]);
        if (rowA + 8 < NNODE)
            *(__half2*)(g_h1 + (size_t)(rowA + 8) * C1 + c0) = __floats2half2_rn(acc[nt][2], acc[nt][3]);
    }
#pragma unroll
    for (int rh = 0; rh < 2; rh++)
#pragma unroll
        for (int hd = 0; hd < 2; hd++) {
            sp[rh][hd] += __shfl_xor_sync(0xffffffffu, sp[rh][hd], 1);
            sp[rh][hd] += __shfl_xor_sync(0xffffffffu, sp[rh][hd], 2);
            dp[rh][hd] += __shfl_xor_sync(0xffffffffu, dp[rh][hd], 1);
            dp[rh][hd] += __shfl_xor_sync(0xffffffffu, dp[rh][hd], 2);
        }
    if (tg == 0) {
#pragma unroll
        for (int rh = 0; rh < 2; rh++) {
            int row = rowA + rh * 8;
            if (row < NNODE) {
                g_als1[row * 2]     = sp[rh][0];  g_ald1[row * 2]     = dp[rh][0];
                g_als1[row * 2 + 1] = sp[rh][1];  g_ald1[row * 2 + 1] = dp[rh][1];
            }
        }
    }
}

// ================= GEMM2: split-bf16 mma.sync + fused logits =================
// CTA: 256 thr (8 warps). Tile 128 rows x 64 cols, K=128 in 2 chunks of 64.
#define SB2_STRIDE 72
#define SB2_BYTES  (64 * SB2_STRIDE * 2)    // 9216 per part
#define SM2_A_HI   0
#define SM2_A_LO   SA_BYTES
#define SM2_B_HI   (2 * SA_BYTES)
#define SM2_B_LO   (2 * SA_BYTES + SB2_BYTES)
#define G2_SMEM    (2 * SA_BYTES + 2 * SB2_BYTES)   // 55296

__global__ void __launch_bounds__(256) gemm2_mma(
        const float* __restrict__ W,
        const float* __restrict__ as, const float* __restrict__ ad) {
    extern __shared__ char smem[];
    uint32_t sb = smem_u32(smem);
    int tid = threadIdx.x;
    int w = tid >> 5, lane = tid & 31;
    int g = lane >> 2, tg = lane & 3;
    int blk = blockIdx.x;

    float acc[8][4];
#pragma unroll
    for (int nt = 0; nt < 8; nt++)
#pragma unroll
        for (int q = 0; q < 4; q++) acc[nt][q] = 0.f;

    uint32_t* sAhi = (uint32_t*)(smem + SM2_A_HI);
    uint32_t* sAlo = (uint32_t*)(smem + SM2_A_LO);
    uint32_t* sBhi = (uint32_t*)(smem + SM2_B_HI);
    uint32_t* sBlo = (uint32_t*)(smem + SM2_B_LO);

    for (int kc = 0; kc < 2; kc++) {
        for (int i = tid; i < 128 * 16; i += 256) {
            int row = i >> 4, q = i & 15;
            int rg = blk * 128 + row; if (rg >= NNODE) rg = NNODE - 1;
            float4 v = __ldg((const float4*)(g_h2 + (size_t)rg * C1 + kc * 64) + q);
            float h0 = __bfloat162float(__float2bfloat16(v.x));
            float h1 = __bfloat162float(__float2bfloat16(v.y));
            float h2 = __bfloat162float(__float2bfloat16(v.z));
            float h3 = __bfloat162float(__float2bfloat16(v.w));
            int o = row * (SA_STRIDE / 2) + q * 2;
            sAhi[o]     = pack_bf16(v.x, v.y);
            sAhi[o + 1] = pack_bf16(v.z, v.w);
            sAlo[o]     = pack_bf16(v.x - h0, v.y - h1);
            sAlo[o + 1] = pack_bf16(v.z - h2, v.w - h3);
        }
        for (int i = tid; i < 64 * 16; i += 256) {
            int kk = i >> 4, q = i & 15;
            float4 v = __ldg((const float4*)(W + (size_t)(kc * 64 + kk) * C2) + q);
            float h0 = __bfloat162float(__float2bfloat16(v.x));
            float h1 = __bfloat162float(__float2bfloat16(v.y));
            float h2 = __bfloat162float(__float2bfloat16(v.z));
            float h3 = __bfloat162float(__float2bfloat16(v.w));
            int o = kk * (SB2_STRIDE / 2) + q * 2;
            sBhi[o]     = pack_bf16(v.x, v.y);
            sBhi[o + 1] = pack_bf16(v.z, v.w);
            sBlo[o]     = pack_bf16(v.x - h0, v.y - h1);
            sBlo[o + 1] = pack_bf16(v.z - h2, v.w - h3);
        }
        __syncthreads();

#pragma unroll
        for (int sub = 0; sub < 4; sub++) {
            int kbase = sub * 16;
            int ar = w * 16 + (lane & 15);
            int ak = kbase + ((lane >> 4) << 3);
            uint32_t aoff = (uint32_t)(ar * SA_STRIDE + ak) * 2;
            uint32_t ahi[4], alo[4];
            asm volatile("ldmatrix.sync.aligned.m8n8.x4.shared.b16 {%0,%1,%2,%3}, [%4];"
                : "=r"(ahi[0]), "=r"(ahi[1]), "=r"(ahi[2]), "=r"(ahi[3])
                : "r"(sb + SM2_A_HI + aoff));
            asm volatile("ldmatrix.sync.aligned.m8n8.x4.shared.b16 {%0,%1,%2,%3}, [%4];"
                : "=r"(alo[0]), "=r"(alo[1]), "=r"(alo[2]), "=r"(alo[3])
                : "r"(sb + SM2_A_LO + aoff));
#pragma unroll
            for (int nt = 0; nt < 8; nt++) {
                uint32_t boff = (uint32_t)((kbase + (lane & 15)) * SB2_STRIDE + nt * 8) * 2;
                uint32_t bh0, bh1, bl0, bl1;
                asm volatile("ldmatrix.sync.aligned.m8n8.x2.trans.shared.b16 {%0,%1}, [%2];"
                    : "=r"(bh0), "=r"(bh1) : "r"(sb + SM2_B_HI + boff));
                asm volatile("ldmatrix.sync.aligned.m8n8.x2.trans.shared.b16 {%0,%1}, [%2];"
                    : "=r"(bl0), "=r"(bl1) : "r"(sb + SM2_B_LO + boff));
                mma16816(acc[nt], ahi, bh0, bh1);
                mma16816(acc[nt], ahi, bl0, bl1);
                mma16816(acc[nt], alo, bh0, bh1);
            }
        }
        __syncthreads();
    }

    // ---- epilogue: store h3 (fp16) + fused logits (single head) ----
    int rowA = blk * 128 + w * 16 + g;
    float sp0 = 0.f, dp0 = 0.f, sp1 = 0.f, dp1 = 0.f;
#pragma unroll
    for (int nt = 0; nt < 8; nt++) {
        int c0 = nt * 8 + tg * 2;
        float a0 = __ldg(as + c0), a1 = __ldg(as + c0 + 1);
        float d0 = __ldg(ad + c0), d1 = __ldg(ad + c0 + 1);
        sp0 += acc[nt][0] * a0 + acc[nt][1] * a1;
        dp0 += acc[nt][0] * d0 + acc[nt][1] * d1;
        sp1 += acc[nt][2] * a0 + acc[nt][3] * a1;
        dp1 += acc[nt][2] * d0 + acc[nt][3] * d1;
        if (rowA < NNODE)
            *(__half2*)(g_h3 + (size_t)rowA * C2 + c0) = __floats2half2_rn(acc[nt][0], acc[nt][1]);
        if (rowA + 8 < NNODE)
            *(__half2*)(g_h3 + (size_t)(rowA + 8) * C2 + c0) = __floats2half2_rn(acc[nt][2], acc[nt][3]);
    }
    sp0 += __shfl_xor_sync(0xffffffffu, sp0, 1); sp0 += __shfl_xor_sync(0xffffffffu, sp0, 2);
    dp0 += __shfl_xor_sync(0xffffffffu, dp0, 1); dp0 += __shfl_xor_sync(0xffffffffu, dp0, 2);
    sp1 += __shfl_xor_sync(0xffffffffu, sp1, 1); sp1 += __shfl_xor_sync(0xffffffffu, sp1, 2);
    dp1 += __shfl_xor_sync(0xffffffffu, dp1, 1); dp1 += __shfl_xor_sync(0xffffffffu, dp1, 2);
    if (tg == 0) {
        if (rowA < NNODE)     { g_als2[rowA] = sp0;     g_ald2[rowA] = dp0; }
        if (rowA + 8 < NNODE) { g_als2[rowA + 8] = sp1; g_ald2[rowA + 8] = dp1; }
    }
}

// ---------------- CSR build ----------------
__global__ void zero_deg() {
    int i = blockIdx.x * blockDim.x + threadIdx.x;
    if (i < NNODE) g_deg[i] = 0;
}

__global__ void hist(const int* __restrict__ ei, int E, int ET) {
    int i = blockIdx.x * blockDim.x + threadIdx.x;
    if (i >= ET) return;
    int d = (i < E) ? __ldg(ei + E + i) : i - E;
    atomicAdd(&g_deg[d], 1);
}

__global__ void scanA() {
    int i = blockIdx.x * 1024 + threadIdx.x;
    int v = (i < NNODE) ? g_deg[i] : 0;
    int lane = threadIdx.x & 31, wid = threadIdx.x >> 5;
    int x = v;
#pragma unroll
    for (int o = 1; o < 32; o <<= 1) {
        int t = __shfl_up_sync(0xffffffffu, x, o);
        if (lane >= o) x += t;
    }
    __shared__ int ws[32];
    if (lane == 31) ws[wid] = x;
    __syncthreads();
    if (wid == 0) {
        int y = ws[lane];
#pragma unroll
        for (int o = 1; o < 32; o <<= 1) {
            int t = __shfl_up_sync(0xffffffffu, y, o);
            if (lane >= o) y += t;
        }
        ws[lane] = y;
    }
    __syncthreads();
    int excl = x - v + (wid > 0 ? ws[wid - 1] : 0);
    if (i < NNODE) g_roff[i] = excl;
    if (threadIdx.x == 0) g_bsum[blockIdx.x] = ws[31];
}

__global__ void scanB(int nb) {
    int t = threadIdx.x;
    int v = (t < nb) ? g_bsum[t] : 0;
    int lane = t & 31, wid = t >> 5;
    int x = v;
#pragma unroll
    for (int o = 1; o < 32; o <<= 1) {
        int u = __shfl_up_sync(0xffffffffu, x, o);
        if (lane >= o) x += u;
    }
    __shared__ int ws[8];
    if (lane == 31) ws[wid] = x;
    __syncthreads();
    int carry = 0;
    for (int k = 0; k < wid; k++) carry += ws[k];
    int excl = x - v + carry;
    if (t < nb) g_bsum[t] = excl;
}

__global__ void scanC() {
    int i = blockIdx.x * blockDim.x + threadIdx.x;
    if (i >= NNODE) return;
    int r = g_roff[i] + g_bsum[i >> 10];
    g_roff[i] = r;
    g_cur[i]  = r;
}

__global__ void scatter(const int* __restrict__ ei, int E, int ET) {
    int i = blockIdx.x * blockDim.x + threadIdx.x;
    if (i >= ET) return;
    int s, d;
    if (i < E) { s = __ldg(ei + i); d = __ldg(ei + E + i); } else { s = d = i - E; }
    int p = atomicAdd(&g_cur[d], 1);
    g_csr[p] = s;
}

// ---------------- layer-1 aggregation (gather, fp16 features) ----------------
__global__ void __launch_bounds__(256) agg1(const float* __restrict__ b1) {
    int n = (int)((blockIdx.x * blockDim.x + threadIdx.x) >> 5);
    if (n >= NNODE) return;
    int lane = threadIdx.x & 31;
    int head = lane >> 4;
    int start = g_roff[n], len = g_deg[n];
    float aldv = __ldg(&g_ald1[n * 2 + head]);
    const int* cp = g_csr + start;

    float4 acc = make_float4(0.f, 0.f, 0.f, 0.f);
    float z = 0.f;

    int s_cur = __ldg(cp);
    float al_cur = __ldg(&g_als1[s_cur * 2 + head]);
    for (int j = 0; j < len; j++) {
        int s_nxt = 0; float al_nxt = 0.f;
        if (j + 1 < len) {
            s_nxt = __ldg(cp + j + 1);
            al_nxt = __ldg(&g_als1[s_nxt * 2 + head]);
        }
        float w = expf(leaky(al_cur + aldv));
        uint2 u = *(const uint2*)(g_h1 + (size_t)s_cur * C1 + lane * 4);
        float2 f0 = __half22float2(*(__half2*)&u.x);
        float2 f1 = __half22float2(*(__half2*)&u.y);
        acc.x = fmaf(w, f0.x, acc.x);
        acc.y = fmaf(w, f0.y, acc.y);
        acc.z = fmaf(w, f1.x, acc.z);
        acc.w = fmaf(w, f1.y, acc.w);
        z += w;
        s_cur = s_nxt; al_cur = al_nxt;
    }
    float inv = 1.f / z;
    float4 bv = __ldg((const float4*)b1 + lane);
    float o0 = fmaf(acc.x, inv, bv.x);
    float o1 = fmaf(acc.y, inv, bv.y);
    float o2 = fmaf(acc.z, inv, bv.z);
    float o3 = fmaf(acc.w, inv, bv.w);
    o0 = o0 > 0.f ? o0 : expm1f(o0);
    o1 = o1 > 0.f ? o1 : expm1f(o1);
    o2 = o2 > 0.f ? o2 : expm1f(o2);
    o3 = o3 > 0.f ? o3 : expm1f(o3);
    *(float4*)(g_h2 + (size_t)n * C1 + lane * 4) = make_float4(o0, o1, o2, o3);
}

// ---------------- layer-2 aggregation (gather, fp16 features) ----------------
__global__ void __launch_bounds__(256) agg2(float* __restrict__ out,
                                            const float* __restrict__ b2) {
    int n = (int)((blockIdx.x * blockDim.x + threadIdx.x) >> 5);
    if (n >= NNODE) return;
    int lane = threadIdx.x & 31;
    int half = lane >> 4, l = lane & 15;
    int start = g_roff[n], len = g_deg[n];
    float aldv = __ldg(&g_ald2[n]);
    const int* cp = g_csr + start;

    float4 acc = make_float4(0.f, 0.f, 0.f, 0.f);
    float z = 0.f;

    int j = half;
    int s_cur = 0; float al_cur = 0.f;
    if (j < len) { s_cur = __ldg(cp + j); al_cur = __ldg(&g_als2[s_cur]); }
    for (; j < len; j += 2) {
        int s_nxt = 0; float al_nxt = 0.f;
        if (j + 2 < len) {
            s_nxt = __ldg(cp + j + 2);
            al_nxt = __ldg(&g_als2[s_nxt]);
        }
        float w = expf(leaky(al_cur + aldv));
        uint2 u = *(const uint2*)(g_h3 + (size_t)s_cur * C2 + l * 4);
        float2 f0 = __half22float2(*(__half2*)&u.x);
        float2 f1 = __half22float2(*(__half2*)&u.y);
        acc.x = fmaf(w, f0.x, acc.x);
        acc.y = fmaf(w, f0.y, acc.y);
        acc.z = fmaf(w, f1.x, acc.z);
        acc.w = fmaf(w, f1.y, acc.w);
        z += w;
        s_cur = s_nxt; al_cur = al_nxt;
    }
    acc.x += __shfl_xor_sync(0xffffffffu, acc.x, 16);
    acc.y += __shfl_xor_sync(0xffffffffu, acc.y, 16);
    acc.z += __shfl_xor_sync(0xffffffffu, acc.z, 16);
    acc.w += __shfl_xor_sync(0xffffffffu, acc.w, 16);
    z     += __shfl_xor_sync(0xffffffffu, z, 16);
    if (half == 0) {
        float inv = 1.f / z;
        float4 bv = __ldg((const float4*)b2 + l);
        *(float4*)(out + (size_t)n * C2 + l * 4) =
            make_float4(fmaf(acc.x, inv, bv.x), fmaf(acc.y, inv, bv.y),
                        fmaf(acc.z, inv, bv.z), fmaf(acc.w, inv, bv.w));
    }
}

// ---------------- launch ----------------
extern "C" void kernel_launch(void* const* d_in, const int* in_sizes, int n_in,
                              void* d_out, int out_size) {
    const float* x      = (const float*)d_in[0];
    const int*   ei     = (const int*)  d_in[1];
    const float* W1     = (const float*)d_in[2];
    const float* a_src1 = (const float*)d_in[3];
    const float* a_dst1 = (const float*)d_in[4];
    const float* b1     = (const float*)d_in[5];
    const float* W2     = (const float*)d_in[6];
    const float* a_src2 = (const float*)d_in[7];
    const float* a_dst2 = (const float*)d_in[8];
    const float* b2     = (const float*)d_in[9];
    float* out = (float*)d_out;

    const int E = in_sizes[1] / 2;
    const int ET = E + NNODE;
    const int TB = 256;
    const int nbScan = (NNODE + 1023) / 1024;

    cudaFuncSetAttribute(gemm1_mma, cudaFuncAttributeMaxDynamicSharedMemorySize, G1_SMEM);
    cudaFuncSetAttribute(gemm2_mma, cudaFuncAttributeMaxDynamicSharedMemorySize, G2_SMEM);

    // CSR build (independent of features)
    zero_deg<<<(NNODE + TB - 1) / TB, TB>>>();
    hist<<<(ET + TB - 1) / TB, TB>>>(ei, E, ET);
    scanA<<<nbScan, 1024>>>();
    scanB<<<1, 256>>>(nbScan);
    scanC<<<(NNODE + TB - 1) / TB, TB>>>();
    scatter<<<(ET + TB - 1) / TB, TB>>>(ei, E, ET);

    // layer 1
    gemm1_mma<<<(NNODE + 127) / 128, 256, G1_SMEM>>>(x, W1, a_src1, a_dst1);
    agg1<<<(NNODE * 32 + TB - 1) / TB, TB>>>(b1);

    // layer 2
    gemm2_mma<<<(NNODE + 127) / 128, 256, G2_SMEM>>>(W2, a_src2, a_dst2);
    agg2<<<(NNODE * 32 + TB - 1) / TB, TB>>>(out, b2);
}

// round 9
// speedup vs baseline: 2.5259x; 1.0635x over previous
#include <cuda_runtime.h>
#include <cuda_bf16.h>
#include <cuda_fp16.h>
#include <math.h>
#include <stdint.h>

#define NNODE 100000
#define DIN   256
#define C1    128   // H1*HID (2 heads x 64)
#define C2    64
#define MAXE  2200000

// ---------------- device scratch ----------------
static __device__ __align__(16) __half g_h1[(size_t)NNODE * C1];  // x @ W1 (fp16)
static __device__ __align__(16) float  g_h2[(size_t)NNODE * C1];  // after agg1+elu (fp32)
static __device__ __align__(16) __half g_h3[(size_t)NNODE * C2];  // h2 @ W2 (fp16)
static __device__ float g_als1[NNODE * 2];
static __device__ float g_ald1[NNODE * 2];
static __device__ float g_als2[NNODE];
static __device__ float g_ald2[NNODE];
static __device__ int g_deg [NNODE];
static __device__ int g_roff[NNODE];
static __device__ int g_cur [NNODE];
static __device__ int g_bsum[256];
static __device__ int g_csr [MAXE];

__device__ __forceinline__ float leaky(float v) { return v > 0.f ? v : 0.2f * v; }

__device__ __forceinline__ uint32_t smem_u32(const void* p) {
    uint32_t a;
    asm("{ .reg .u64 t; cvta.to.shared.u64 t, %1; cvt.u32.u64 %0, t; }" : "=r"(a) : "l"(p));
    return a;
}

__device__ __forceinline__ uint32_t pack_bf16(float a, float b) {
    return (uint32_t)__bfloat16_as_ushort(__float2bfloat16(a)) |
           ((uint32_t)__bfloat16_as_ushort(__float2bfloat16(b)) << 16);
}

__device__ __forceinline__ void mma16816(float* d, const uint32_t* a, uint32_t b0, uint32_t b1) {
    asm volatile(
        "mma.sync.aligned.m16n8k16.row.col.f32.bf16.bf16.f32 "
        "{%0,%1,%2,%3}, {%4,%5,%6,%7}, {%8,%9}, {%0,%1,%2,%3};"
        : "+f"(d[0]), "+f"(d[1]), "+f"(d[2]), "+f"(d[3])
        : "r"(a[0]), "r"(a[1]), "r"(a[2]), "r"(a[3]), "r"(b0), "r"(b1));
}

// ================= GEMM1: split-bf16 mma.sync + fused logits =================
#define SA_STRIDE 72      // bf16 units
#define SB_STRIDE 136
#define SA_BYTES  (128 * SA_STRIDE * 2)
#define SB_BYTES  (64 * SB_STRIDE * 2)
#define SM_A_HI   0
#define SM_A_LO   SA_BYTES
#define SM_B_HI   (2 * SA_BYTES)
#define SM_B_LO   (2 * SA_BYTES + SB_BYTES)
#define G1_SMEM   (2 * SA_BYTES + 2 * SB_BYTES)   // 71680

__global__ void __launch_bounds__(256) gemm1_mma(
        const float* __restrict__ X, const float* __restrict__ W,
        const float* __restrict__ as, const float* __restrict__ ad) {
    extern __shared__ char smem[];
    uint32_t sb = smem_u32(smem);
    int tid = threadIdx.x;
    int w = tid >> 5, lane = tid & 31;
    int g = lane >> 2, tg = lane & 3;
    int blk = blockIdx.x;

    float acc[16][4];
#pragma unroll
    for (int nt = 0; nt < 16; nt++)
#pragma unroll
        for (int q = 0; q < 4; q++) acc[nt][q] = 0.f;

    uint32_t* sAhi = (uint32_t*)(smem + SM_A_HI);
    uint32_t* sAlo = (uint32_t*)(smem + SM_A_LO);
    uint32_t* sBhi = (uint32_t*)(smem + SM_B_HI);
    uint32_t* sBlo = (uint32_t*)(smem + SM_B_LO);

    for (int kc = 0; kc < 4; kc++) {
        for (int i = tid; i < 128 * 16; i += 256) {
            int row = i >> 4, q = i & 15;
            int rg = blk * 128 + row; if (rg >= NNODE) rg = NNODE - 1;
            float4 v = __ldg((const float4*)(X + (size_t)rg * DIN + kc * 64) + q);
            float h0 = __bfloat162float(__float2bfloat16(v.x));
            float h1 = __bfloat162float(__float2bfloat16(v.y));
            float h2 = __bfloat162float(__float2bfloat16(v.z));
            float h3 = __bfloat162float(__float2bfloat16(v.w));
            int o = row * (SA_STRIDE / 2) + q * 2;
            sAhi[o]     = pack_bf16(v.x, v.y);
            sAhi[o + 1] = pack_bf16(v.z, v.w);
            sAlo[o]     = pack_bf16(v.x - h0, v.y - h1);
            sAlo[o + 1] = pack_bf16(v.z - h2, v.w - h3);
        }
        for (int i = tid; i < 64 * 32; i += 256) {
            int kk = i >> 5, q = i & 31;
            float4 v = __ldg((const float4*)(W + (size_t)(kc * 64 + kk) * C1) + q);
            float h0 = __bfloat162float(__float2bfloat16(v.x));
            float h1 = __bfloat162float(__float2bfloat16(v.y));
            float h2 = __bfloat162float(__float2bfloat16(v.z));
            float h3 = __bfloat162float(__float2bfloat16(v.w));
            int o = kk * (SB_STRIDE / 2) + q * 2;
            sBhi[o]     = pack_bf16(v.x, v.y);
            sBhi[o + 1] = pack_bf16(v.z, v.w);
            sBlo[o]     = pack_bf16(v.x - h0, v.y - h1);
            sBlo[o + 1] = pack_bf16(v.z - h2, v.w - h3);
        }
        __syncthreads();

#pragma unroll
        for (int sub = 0; sub < 4; sub++) {
            int kbase = sub * 16;
            int ar = w * 16 + (lane & 15);
            int ak = kbase + ((lane >> 4) << 3);
            uint32_t aoff = (uint32_t)(ar * SA_STRIDE + ak) * 2;
            uint32_t ahi[4], alo[4];
            asm volatile("ldmatrix.sync.aligned.m8n8.x4.shared.b16 {%0,%1,%2,%3}, [%4];"
                : "=r"(ahi[0]), "=r"(ahi[1]), "=r"(ahi[2]), "=r"(ahi[3])
                : "r"(sb + SM_A_HI + aoff));
            asm volatile("ldmatrix.sync.aligned.m8n8.x4.shared.b16 {%0,%1,%2,%3}, [%4];"
                : "=r"(alo[0]), "=r"(alo[1]), "=r"(alo[2]), "=r"(alo[3])
                : "r"(sb + SM_A_LO + aoff));
#pragma unroll
            for (int nt = 0; nt < 16; nt++) {
                uint32_t boff = (uint32_t)((kbase + (lane & 15)) * SB_STRIDE + nt * 8) * 2;
                uint32_t bh0, bh1, bl0, bl1;
                asm volatile("ldmatrix.sync.aligned.m8n8.x2.trans.shared.b16 {%0,%1}, [%2];"
                    : "=r"(bh0), "=r"(bh1) : "r"(sb + SM_B_HI + boff));
                asm volatile("ldmatrix.sync.aligned.m8n8.x2.trans.shared.b16 {%0,%1}, [%2];"
                    : "=r"(bl0), "=r"(bl1) : "r"(sb + SM_B_LO + boff));
                mma16816(acc[nt], ahi, bh0, bh1);
                mma16816(acc[nt], ahi, bl0, bl1);
                mma16816(acc[nt], alo, bh0, bh1);
            }
        }
        __syncthreads();
    }

    int rowA = blk * 128 + w * 16 + g;
    float sp[2][2] = {{0.f, 0.f}, {0.f, 0.f}};
    float dp[2][2] = {{0.f, 0.f}, {0.f, 0.f}};
#pragma unroll
    for (int nt = 0; nt < 16; nt++) {
        int c0 = nt * 8 + tg * 2;
        int head = nt >> 3;
        float a0 = __ldg(as + c0), a1 = __ldg(as + c0 + 1);
        float d0 = __ldg(ad + c0), d1 = __ldg(ad + c0 + 1);
        sp[0][head] += acc[nt][0] * a0 + acc[nt][1] * a1;
        dp[0][head] += acc[nt][0] * d0 + acc[nt][1] * d1;
        sp[1][head] += acc[nt][2] * a0 + acc[nt][3] * a1;
        dp[1][head] += acc[nt][2] * d0 + acc[nt][3] * d1;
        if (rowA < NNODE)
            *(__half2*)(g_h1 + (size_t)rowA * C1 + c0) = __floats2half2_rn(acc[nt][0], acc[nt][1]);
        if (rowA + 8 < NNODE)
            *(__half2*)(g_h1 + (size_t)(rowA + 8) * C1 + c0) = __floats2half2_rn(acc[nt][2], acc[nt][3]);
    }
#pragma unroll
    for (int rh = 0; rh < 2; rh++)
#pragma unroll
        for (int hd = 0; hd < 2; hd++) {
            sp[rh][hd] += __shfl_xor_sync(0xffffffffu, sp[rh][hd], 1);
            sp[rh][hd] += __shfl_xor_sync(0xffffffffu, sp[rh][hd], 2);
            dp[rh][hd] += __shfl_xor_sync(0xffffffffu, dp[rh][hd], 1);
            dp[rh][hd] += __shfl_xor_sync(0xffffffffu, dp[rh][hd], 2);
        }
    if (tg == 0) {
#pragma unroll
        for (int rh = 0; rh < 2; rh++) {
            int row = rowA + rh * 8;
            if (row < NNODE) {
                g_als1[row * 2]     = sp[rh][0];  g_ald1[row * 2]     = dp[rh][0];
                g_als1[row * 2 + 1] = sp[rh][1];  g_ald1[row * 2 + 1] = dp[rh][1];
            }
        }
    }
}

// ================= GEMM2: split-bf16 mma.sync + fused logits =================
#define SB2_STRIDE 72
#define SB2_BYTES  (64 * SB2_STRIDE * 2)
#define SM2_A_HI   0
#define SM2_A_LO   SA_BYTES
#define SM2_B_HI   (2 * SA_BYTES)
#define SM2_B_LO   (2 * SA_BYTES + SB2_BYTES)
#define G2_SMEM    (2 * SA_BYTES + 2 * SB2_BYTES)   // 55296

__global__ void __launch_bounds__(256) gemm2_mma(
        const float* __restrict__ W,
        const float* __restrict__ as, const float* __restrict__ ad) {
    extern __shared__ char smem[];
    uint32_t sb = smem_u32(smem);
    int tid = threadIdx.x;
    int w = tid >> 5, lane = tid & 31;
    int g = lane >> 2, tg = lane & 3;
    int blk = blockIdx.x;

    float acc[8][4];
#pragma unroll
    for (int nt = 0; nt < 8; nt++)
#pragma unroll
        for (int q = 0; q < 4; q++) acc[nt][q] = 0.f;

    uint32_t* sAhi = (uint32_t*)(smem + SM2_A_HI);
    uint32_t* sAlo = (uint32_t*)(smem + SM2_A_LO);
    uint32_t* sBhi = (uint32_t*)(smem + SM2_B_HI);
    uint32_t* sBlo = (uint32_t*)(smem + SM2_B_LO);

    for (int kc = 0; kc < 2; kc++) {
        for (int i = tid; i < 128 * 16; i += 256) {
            int row = i >> 4, q = i & 15;
            int rg = blk * 128 + row; if (rg >= NNODE) rg = NNODE - 1;
            float4 v = __ldg((const float4*)(g_h2 + (size_t)rg * C1 + kc * 64) + q);
            float h0 = __bfloat162float(__float2bfloat16(v.x));
            float h1 = __bfloat162float(__float2bfloat16(v.y));
            float h2 = __bfloat162float(__float2bfloat16(v.z));
            float h3 = __bfloat162float(__float2bfloat16(v.w));
            int o = row * (SA_STRIDE / 2) + q * 2;
            sAhi[o]     = pack_bf16(v.x, v.y);
            sAhi[o + 1] = pack_bf16(v.z, v.w);
            sAlo[o]     = pack_bf16(v.x - h0, v.y - h1);
            sAlo[o + 1] = pack_bf16(v.z - h2, v.w - h3);
        }
        for (int i = tid; i < 64 * 16; i += 256) {
            int kk = i >> 4, q = i & 15;
            float4 v = __ldg((const float4*)(W + (size_t)(kc * 64 + kk) * C2) + q);
            float h0 = __bfloat162float(__float2bfloat16(v.x));
            float h1 = __bfloat162float(__float2bfloat16(v.y));
            float h2 = __bfloat162float(__float2bfloat16(v.z));
            float h3 = __bfloat162float(__float2bfloat16(v.w));
            int o = kk * (SB2_STRIDE / 2) + q * 2;
            sBhi[o]     = pack_bf16(v.x, v.y);
            sBhi[o + 1] = pack_bf16(v.z, v.w);
            sBlo[o]     = pack_bf16(v.x - h0, v.y - h1);
            sBlo[o + 1] = pack_bf16(v.z - h2, v.w - h3);
        }
        __syncthreads();

#pragma unroll
        for (int sub = 0; sub < 4; sub++) {
            int kbase = sub * 16;
            int ar = w * 16 + (lane & 15);
            int ak = kbase + ((lane >> 4) << 3);
            uint32_t aoff = (uint32_t)(ar * SA_STRIDE + ak) * 2;
            uint32_t ahi[4], alo[4];
            asm volatile("ldmatrix.sync.aligned.m8n8.x4.shared.b16 {%0,%1,%2,%3}, [%4];"
                : "=r"(ahi[0]), "=r"(ahi[1]), "=r"(ahi[2]), "=r"(ahi[3])
                : "r"(sb + SM2_A_HI + aoff));
            asm volatile("ldmatrix.sync.aligned.m8n8.x4.shared.b16 {%0,%1,%2,%3}, [%4];"
                : "=r"(alo[0]), "=r"(alo[1]), "=r"(alo[2]), "=r"(alo[3])
                : "r"(sb + SM2_A_LO + aoff));
#pragma unroll
            for (int nt = 0; nt < 8; nt++) {
                uint32_t boff = (uint32_t)((kbase + (lane & 15)) * SB2_STRIDE + nt * 8) * 2;
                uint32_t bh0, bh1, bl0, bl1;
                asm volatile("ldmatrix.sync.aligned.m8n8.x2.trans.shared.b16 {%0,%1}, [%2];"
                    : "=r"(bh0), "=r"(bh1) : "r"(sb + SM2_B_HI + boff));
                asm volatile("ldmatrix.sync.aligned.m8n8.x2.trans.shared.b16 {%0,%1}, [%2];"
                    : "=r"(bl0), "=r"(bl1) : "r"(sb + SM2_B_LO + boff));
                mma16816(acc[nt], ahi, bh0, bh1);
                mma16816(acc[nt], ahi, bl0, bl1);
                mma16816(acc[nt], alo, bh0, bh1);
            }
        }
        __syncthreads();
    }

    int rowA = blk * 128 + w * 16 + g;
    float sp0 = 0.f, dp0 = 0.f, sp1 = 0.f, dp1 = 0.f;
#pragma unroll
    for (int nt = 0; nt < 8; nt++) {
        int c0 = nt * 8 + tg * 2;
        float a0 = __ldg(as + c0), a1 = __ldg(as + c0 + 1);
        float d0 = __ldg(ad + c0), d1 = __ldg(ad + c0 + 1);
        sp0 += acc[nt][0] * a0 + acc[nt][1] * a1;
        dp0 += acc[nt][0] * d0 + acc[nt][1] * d1;
        sp1 += acc[nt][2] * a0 + acc[nt][3] * a1;
        dp1 += acc[nt][2] * d0 + acc[nt][3] * d1;
        if (rowA < NNODE)
            *(__half2*)(g_h3 + (size_t)rowA * C2 + c0) = __floats2half2_rn(acc[nt][0], acc[nt][1]);
        if (rowA + 8 < NNODE)
            *(__half2*)(g_h3 + (size_t)(rowA + 8) * C2 + c0) = __floats2half2_rn(acc[nt][2], acc[nt][3]);
    }
    sp0 += __shfl_xor_sync(0xffffffffu, sp0, 1); sp0 += __shfl_xor_sync(0xffffffffu, sp0, 2);
    dp0 += __shfl_xor_sync(0xffffffffu, dp0, 1); dp0 += __shfl_xor_sync(0xffffffffu, dp0, 2);
    sp1 += __shfl_xor_sync(0xffffffffu, sp1, 1); sp1 += __shfl_xor_sync(0xffffffffu, sp1, 2);
    dp1 += __shfl_xor_sync(0xffffffffu, dp1, 1); dp1 += __shfl_xor_sync(0xffffffffu, dp1, 2);
    if (tg == 0) {
        if (rowA < NNODE)     { g_als2[rowA] = sp0;     g_ald2[rowA] = dp0; }
        if (rowA + 8 < NNODE) { g_als2[rowA + 8] = sp1; g_ald2[rowA + 8] = dp1; }
    }
}

// ---------------- CSR build ----------------
__global__ void zero_deg() {
    int i = blockIdx.x * blockDim.x + threadIdx.x;
    if (i < NNODE) g_deg[i] = 0;
}

__global__ void hist(const int* __restrict__ ei, int E, int ET) {
    int i = blockIdx.x * blockDim.x + threadIdx.x;
    if (i >= ET) return;
    int d = (i < E) ? __ldg(ei + E + i) : i - E;
    atomicAdd(&g_deg[d], 1);
}

__global__ void scanA() {
    int i = blockIdx.x * 1024 + threadIdx.x;
    int v = (i < NNODE) ? g_deg[i] : 0;
    int lane = threadIdx.x & 31, wid = threadIdx.x >> 5;
    int x = v;
#pragma unroll
    for (int o = 1; o < 32; o <<= 1) {
        int t = __shfl_up_sync(0xffffffffu, x, o);
        if (lane >= o) x += t;
    }
    __shared__ int ws[32];
    if (lane == 31) ws[wid] = x;
    __syncthreads();
    if (wid == 0) {
        int y = ws[lane];
#pragma unroll
        for (int o = 1; o < 32; o <<= 1) {
            int t = __shfl_up_sync(0xffffffffu, y, o);
            if (lane >= o) y += t;
        }
        ws[lane] = y;
    }
    __syncthreads();
    int excl = x - v + (wid > 0 ? ws[wid - 1] : 0);
    if (i < NNODE) g_roff[i] = excl;
    if (threadIdx.x == 0) g_bsum[blockIdx.x] = ws[31];
}

__global__ void scanB(int nb) {
    int t = threadIdx.x;
    int v = (t < nb) ? g_bsum[t] : 0;
    int lane = t & 31, wid = t >> 5;
    int x = v;
#pragma unroll
    for (int o = 1; o < 32; o <<= 1) {
        int u = __shfl_up_sync(0xffffffffu, x, o);
        if (lane >= o) x += u;
    }
    __shared__ int ws[8];
    if (lane == 31) ws[wid] = x;
    __syncthreads();
    int carry = 0;
    for (int k = 0; k < wid; k++) carry += ws[k];
    int excl = x - v + carry;
    if (t < nb) g_bsum[t] = excl;
}

__global__ void scanC() {
    int i = blockIdx.x * blockDim.x + threadIdx.x;
    if (i >= NNODE) return;
    int r = g_roff[i] + g_bsum[i >> 10];
    g_roff[i] = r;
    g_cur[i]  = r;
}

__global__ void scatter(const int* __restrict__ ei, int E, int ET) {
    int i = blockIdx.x * blockDim.x + threadIdx.x;
    if (i >= ET) return;
    int s, d;
    if (i < E) { s = __ldg(ei + i); d = __ldg(ei + E + i); } else { s = d = i - E; }
    int p = atomicAdd(&g_cur[d], 1);
    g_csr[p] = s;
}

// ---------------- layer-1 aggregation: depth-2 pipelined gather ----------------
__global__ void __launch_bounds__(256) agg1(const float* __restrict__ b1) {
    int n = (int)((blockIdx.x * blockDim.x + threadIdx.x) >> 5);
    if (n >= NNODE) return;
    int lane = threadIdx.x & 31;
    int head = lane >> 4;
    int start = g_roff[n], len = g_deg[n];
    float aldv = __ldg(&g_ald1[n * 2 + head]);
    const int* cp = g_csr + start;

    float4 acc = make_float4(0.f, 0.f, 0.f, 0.f);
    float z = 0.f;

    int s0, s1 = 0;
    float al0, al1 = 0.f;
    uint2 u0, u1 = make_uint2(0u, 0u);
    s0 = __ldg(cp);                                   // len >= 1 (self loop)
    al0 = __ldg(&g_als1[s0 * 2 + head]);
    u0 = *(const uint2*)(g_h1 + (size_t)s0 * C1 + lane * 4);
    if (len > 1) {
        s1 = __ldg(cp + 1);
        al1 = __ldg(&g_als1[s1 * 2 + head]);
        u1 = *(const uint2*)(g_h1 + (size_t)s1 * C1 + lane * 4);
    }
    for (int j = 0; j < len; j++) {
        int s2 = 0; float al2 = 0.f; uint2 u2 = make_uint2(0u, 0u);
        if (j + 2 < len) {
            s2 = __ldg(cp + j + 2);
            al2 = __ldg(&g_als1[s2 * 2 + head]);
            u2 = *(const uint2*)(g_h1 + (size_t)s2 * C1 + lane * 4);
        }
        float w = expf(leaky(al0 + aldv));
        float2 f0 = __half22float2(*(__half2*)&u0.x);
        float2 f1 = __half22float2(*(__half2*)&u0.y);
        acc.x = fmaf(w, f0.x, acc.x);
        acc.y = fmaf(w, f0.y, acc.y);
        acc.z = fmaf(w, f1.x, acc.z);
        acc.w = fmaf(w, f1.y, acc.w);
        z += w;
        s0 = s1; al0 = al1; u0 = u1;
        s1 = s2; al1 = al2; u1 = u2;
    }
    float inv = 1.f / z;
    float4 bv = __ldg((const float4*)b1 + lane);
    float o0 = fmaf(acc.x, inv, bv.x);
    float o1 = fmaf(acc.y, inv, bv.y);
    float o2 = fmaf(acc.z, inv, bv.z);
    float o3 = fmaf(acc.w, inv, bv.w);
    o0 = o0 > 0.f ? o0 : expm1f(o0);
    o1 = o1 > 0.f ? o1 : expm1f(o1);
    o2 = o2 > 0.f ? o2 : expm1f(o2);
    o3 = o3 > 0.f ? o3 : expm1f(o3);
    *(float4*)(g_h2 + (size_t)n * C1 + lane * 4) = make_float4(o0, o1, o2, o3);
}

// ---------------- layer-2 aggregation: depth-2 pipelined, 2 edges/warp ----------------
__global__ void __launch_bounds__(256) agg2(float* __restrict__ out,
                                            const float* __restrict__ b2) {
    int n = (int)((blockIdx.x * blockDim.x + threadIdx.x) >> 5);
    if (n >= NNODE) return;
    int lane = threadIdx.x & 31;
    int half = lane >> 4, l = lane & 15;
    int start = g_roff[n], len = g_deg[n];
    float aldv = __ldg(&g_ald2[n]);
    const int* cp = g_csr + start;

    float4 acc = make_float4(0.f, 0.f, 0.f, 0.f);
    float z = 0.f;

    int s0 = 0, s1 = 0;
    float al0 = 0.f, al1 = 0.f;
    uint2 u0 = make_uint2(0u, 0u), u1 = make_uint2(0u, 0u);
    if (half < len) {
        s0 = __ldg(cp + half);
        al0 = __ldg(&g_als2[s0]);
        u0 = *(const uint2*)(g_h3 + (size_t)s0 * C2 + l * 4);
    }
    if (half + 2 < len) {
        s1 = __ldg(cp + half + 2);
        al1 = __ldg(&g_als2[s1]);
        u1 = *(const uint2*)(g_h3 + (size_t)s1 * C2 + l * 4);
    }
    for (int j = half; j < len; j += 2) {
        int s2 = 0; float al2 = 0.f; uint2 u2 = make_uint2(0u, 0u);
        if (j + 4 < len) {
            s2 = __ldg(cp + j + 4);
            al2 = __ldg(&g_als2[s2]);
            u2 = *(const uint2*)(g_h3 + (size_t)s2 * C2 + l * 4);
        }
        float w = expf(leaky(al0 + aldv));
        float2 f0 = __half22float2(*(__half2*)&u0.x);
        float2 f1 = __half22float2(*(__half2*)&u0.y);
        acc.x = fmaf(w, f0.x, acc.x);
        acc.y = fmaf(w, f0.y, acc.y);
        acc.z = fmaf(w, f1.x, acc.z);
        acc.w = fmaf(w, f1.y, acc.w);
        z += w;
        s0 = s1; al0 = al1; u0 = u1;
        s1 = s2; al1 = al2; u1 = u2;
    }
    acc.x += __shfl_xor_sync(0xffffffffu, acc.x, 16);
    acc.y += __shfl_xor_sync(0xffffffffu, acc.y, 16);
    acc.z += __shfl_xor_sync(0xffffffffu, acc.z, 16);
    acc.w += __shfl_xor_sync(0xffffffffu, acc.w, 16);
    z     += __shfl_xor_sync(0xffffffffu, z, 16);
    if (half == 0) {
        float inv = 1.f / z;
        float4 bv = __ldg((const float4*)b2 + l);
        *(float4*)(out + (size_t)n * C2 + l * 4) =
            make_float4(fmaf(acc.x, inv, bv.x), fmaf(acc.y, inv, bv.y),
                        fmaf(acc.z, inv, bv.z), fmaf(acc.w, inv, bv.w));
    }
}

// ---------------- launch ----------------
extern "C" void kernel_launch(void* const* d_in, const int* in_sizes, int n_in,
                              void* d_out, int out_size) {
    const float* x      = (const float*)d_in[0];
    const int*   ei     = (const int*)  d_in[1];
    const float* W1     = (const float*)d_in[2];
    const float* a_src1 = (const float*)d_in[3];
    const float* a_dst1 = (const float*)d_in[4];
    const float* b1     = (const float*)d_in[5];
    const float* W2     = (const float*)d_in[6];
    const float* a_src2 = (const float*)d_in[7];
    const float* a_dst2 = (const float*)d_in[8];
    const float* b2     = (const float*)d_in[9];
    float* out = (float*)d_out;

    const int E = in_sizes[1] / 2;
    const int ET = E + NNODE;
    const int TB = 256;
    const int nbScan = (NNODE + 1023) / 1024;

    // static infra; created on the first (non-captured) call, guarded with fallback
    static cudaStream_t sCsr = nullptr;
    static cudaEvent_t evFork = nullptr, evJoin = nullptr;
    static int forkOk = -1;   // -1 = not attempted, 0 = fallback serial, 1 = fork
    if (forkOk == -1) {
        cudaFuncSetAttribute(gemm1_mma, cudaFuncAttributeMaxDynamicSharedMemorySize, G1_SMEM);
        cudaFuncSetAttribute(gemm2_mma, cudaFuncAttributeMaxDynamicSharedMemorySize, G2_SMEM);
        cudaError_t e1 = cudaStreamCreateWithFlags(&sCsr, cudaStreamNonBlocking);
        cudaError_t e2 = cudaEventCreateWithFlags(&evFork, cudaEventDisableTiming);
        cudaError_t e3 = cudaEventCreateWithFlags(&evJoin, cudaEventDisableTiming);
        forkOk = (e1 == cudaSuccess && e2 == cudaSuccess && e3 == cudaSuccess) ? 1 : 0;
    }

    if (forkOk == 1) {
        // fork: CSR build on sCsr, overlapped with gemm1 on the default stream
        cudaEventRecord(evFork, 0);
        cudaStreamWaitEvent(sCsr, evFork, 0);

        zero_deg<<<(NNODE + TB - 1) / TB, TB, 0, sCsr>>>();
        hist<<<(ET + TB - 1) / TB, TB, 0, sCsr>>>(ei, E, ET);
        scanA<<<nbScan, 1024, 0, sCsr>>>();
        scanB<<<1, 256, 0, sCsr>>>(nbScan);
        scanC<<<(NNODE + TB - 1) / TB, TB, 0, sCsr>>>();
        scatter<<<(ET + TB - 1) / TB, TB, 0, sCsr>>>(ei, E, ET);
        cudaEventRecord(evJoin, sCsr);

        gemm1_mma<<<(NNODE + 127) / 128, 256, G1_SMEM>>>(x, W1, a_src1, a_dst1);

        cudaStreamWaitEvent(0, evJoin, 0);
    } else {
        // serial fallback
        zero_deg<<<(NNODE + TB - 1) / TB, TB>>>();
        hist<<<(ET + TB - 1) / TB, TB>>>(ei, E, ET);
        scanA<<<nbScan, 1024>>>();
        scanB<<<1, 256>>>(nbScan);
        scanC<<<(NNODE + TB - 1) / TB, TB>>>();
        scatter<<<(ET + TB - 1) / TB, TB>>>(ei, E, ET);
        gemm1_mma<<<(NNODE + 127) / 128, 256, G1_SMEM>>>(x, W1, a_src1, a_dst1);
    }

    agg1<<<(NNODE * 32 + TB - 1) / TB, TB>>>(b1);

    // layer 2
    gemm2_mma<<<(NNODE + 127) / 128, 256, G2_SMEM>>>(W2, a_src2, a_dst2);
    agg2<<<(NNODE * 32 + TB - 1) / TB, TB>>>(out, b2);
}

// round 10
// speedup vs baseline: 3.1092x; 1.2309x over previous
#include <cuda_runtime.h>
#include <cuda_fp16.h>
#include <math.h>
#include <stdint.h>

#define NNODE 100000
#define DIN   256
#define C1    128   // H1*HID (2 heads x 64)
#define C2    64
#define MAXE  2200000

// ---------------- device scratch ----------------
static __device__ __align__(16) __half g_h1[(size_t)NNODE * C1];  // x @ W1 (fp16)
static __device__ __align__(16) float  g_h2[(size_t)NNODE * C1];  // after agg1+elu (fp32)
static __device__ __align__(16) __half g_h3[(size_t)NNODE * C2];  // h2 @ W2 (fp16)
static __device__ float g_als1[NNODE * 2];
static __device__ float g_ald1[NNODE * 2];
static __device__ float g_als2[NNODE];
static __device__ float g_ald2[NNODE];
static __device__ int g_deg [NNODE];
static __device__ int g_roff[NNODE];
static __device__ int g_cur [NNODE];
static __device__ int g_bsum[256];
static __device__ int g_csr [MAXE];

__device__ __forceinline__ float leaky(float v) { return v > 0.f ? v : 0.2f * v; }

__device__ __forceinline__ uint32_t smem_u32(const void* p) {
    uint32_t a;
    asm("{ .reg .u64 t; cvta.to.shared.u64 t, %1; cvt.u32.u64 %0, t; }" : "=r"(a) : "l"(p));
    return a;
}

__device__ __forceinline__ uint32_t pack_f16(float a, float b) {
    __half2 h = __floats2half2_rn(a, b);
    return *(uint32_t*)&h;
}

__device__ __forceinline__ void mma16816h(float* d, const uint32_t* a, uint32_t b0, uint32_t b1) {
    asm volatile(
        "mma.sync.aligned.m16n8k16.row.col.f32.f16.f16.f32 "
        "{%0,%1,%2,%3}, {%4,%5,%6,%7}, {%8,%9}, {%0,%1,%2,%3};"
        : "+f"(d[0]), "+f"(d[1]), "+f"(d[2]), "+f"(d[3])
        : "r"(a[0]), "r"(a[1]), "r"(a[2]), "r"(a[3]), "r"(b0), "r"(b1));
}

// ================= GEMM1: fp16 mma.sync + fused logits =================
// CTA: 256 thr (8 warps). Tile 128 rows x 128 cols, K=256 in 4 chunks of 64.
#define SA_STRIDE 72      // f16 units
#define SB_STRIDE 136
#define SA_BYTES  (128 * SA_STRIDE * 2)     // 18432
#define SB_BYTES  (64 * SB_STRIDE * 2)      // 17408
#define SM_A      0
#define SM_B      SA_BYTES
#define G1_SMEM   (SA_BYTES + SB_BYTES)     // 35840

__global__ void __launch_bounds__(256) gemm1_mma(
        const float* __restrict__ X, const float* __restrict__ W,
        const float* __restrict__ as, const float* __restrict__ ad) {
    extern __shared__ char smem[];
    uint32_t sb = smem_u32(smem);
    int tid = threadIdx.x;
    int w = tid >> 5, lane = tid & 31;
    int g = lane >> 2, tg = lane & 3;
    int blk = blockIdx.x;

    float acc[16][4];
#pragma unroll
    for (int nt = 0; nt < 16; nt++)
#pragma unroll
        for (int q = 0; q < 4; q++) acc[nt][q] = 0.f;

    uint32_t* sA = (uint32_t*)(smem + SM_A);
    uint32_t* sB = (uint32_t*)(smem + SM_B);

    for (int kc = 0; kc < 4; kc++) {
        for (int i = tid; i < 128 * 16; i += 256) {
            int row = i >> 4, q = i & 15;
            int rg = blk * 128 + row; if (rg >= NNODE) rg = NNODE - 1;
            float4 v = __ldg((const float4*)(X + (size_t)rg * DIN + kc * 64) + q);
            int o = row * (SA_STRIDE / 2) + q * 2;
            sA[o]     = pack_f16(v.x, v.y);
            sA[o + 1] = pack_f16(v.z, v.w);
        }
        for (int i = tid; i < 64 * 32; i += 256) {
            int kk = i >> 5, q = i & 31;
            float4 v = __ldg((const float4*)(W + (size_t)(kc * 64 + kk) * C1) + q);
            int o = kk * (SB_STRIDE / 2) + q * 2;
            sB[o]     = pack_f16(v.x, v.y);
            sB[o + 1] = pack_f16(v.z, v.w);
        }
        __syncthreads();

#pragma unroll
        for (int sub = 0; sub < 4; sub++) {
            int kbase = sub * 16;
            int ar = w * 16 + (lane & 15);
            int ak = kbase + ((lane >> 4) << 3);
            uint32_t aoff = (uint32_t)(ar * SA_STRIDE + ak) * 2;
            uint32_t af[4];
            asm volatile("ldmatrix.sync.aligned.m8n8.x4.shared.b16 {%0,%1,%2,%3}, [%4];"
                : "=r"(af[0]), "=r"(af[1]), "=r"(af[2]), "=r"(af[3])
                : "r"(sb + SM_A + aoff));
#pragma unroll
            for (int nt = 0; nt < 16; nt++) {
                uint32_t boff = (uint32_t)((kbase + (lane & 15)) * SB_STRIDE + nt * 8) * 2;
                uint32_t b0, b1;
                asm volatile("ldmatrix.sync.aligned.m8n8.x2.trans.shared.b16 {%0,%1}, [%2];"
                    : "=r"(b0), "=r"(b1) : "r"(sb + SM_B + boff));
                mma16816h(acc[nt], af, b0, b1);
            }
        }
        __syncthreads();
    }

    int rowA = blk * 128 + w * 16 + g;
    float sp[2][2] = {{0.f, 0.f}, {0.f, 0.f}};
    float dp[2][2] = {{0.f, 0.f}, {0.f, 0.f}};
#pragma unroll
    for (int nt = 0; nt < 16; nt++) {
        int c0 = nt * 8 + tg * 2;
        int head = nt >> 3;
        float a0 = __ldg(as + c0), a1 = __ldg(as + c0 + 1);
        float d0 = __ldg(ad + c0), d1 = __ldg(ad + c0 + 1);
        sp[0][head] += acc[nt][0] * a0 + acc[nt][1] * a1;
        dp[0][head] += acc[nt][0] * d0 + acc[nt][1] * d1;
        sp[1][head] += acc[nt][2] * a0 + acc[nt][3] * a1;
        dp[1][head] += acc[nt][2] * d0 + acc[nt][3] * d1;
        if (rowA < NNODE)
            *(__half2*)(g_h1 + (size_t)rowA * C1 + c0) = __floats2half2_rn(acc[nt][0], acc[nt][1]);
        if (rowA + 8 < NNODE)
            *(__half2*)(g_h1 + (size_t)(rowA + 8) * C1 + c0) = __floats2half2_rn(acc[nt][2], acc[nt][3]);
    }
#pragma unroll
    for (int rh = 0; rh < 2; rh++)
#pragma unroll
        for (int hd = 0; hd < 2; hd++) {
            sp[rh][hd] += __shfl_xor_sync(0xffffffffu, sp[rh][hd], 1);
            sp[rh][hd] += __shfl_xor_sync(0xffffffffu, sp[rh][hd], 2);
            dp[rh][hd] += __shfl_xor_sync(0xffffffffu, dp[rh][hd], 1);
            dp[rh][hd] += __shfl_xor_sync(0xffffffffu, dp[rh][hd], 2);
        }
    if (tg == 0) {
#pragma unroll
        for (int rh = 0; rh < 2; rh++) {
            int row = rowA + rh * 8;
            if (row < NNODE) {
                g_als1[row * 2]     = sp[rh][0];  g_ald1[row * 2]     = dp[rh][0];
                g_als1[row * 2 + 1] = sp[rh][1];  g_ald1[row * 2 + 1] = dp[rh][1];
            }
        }
    }
}

// ================= GEMM2: fp16 mma.sync + fused logits =================
#define SB2_STRIDE 72
#define SB2_BYTES  (64 * SB2_STRIDE * 2)    // 9216
#define SM2_A      0
#define SM2_B      SA_BYTES
#define G2_SMEM    (SA_BYTES + SB2_BYTES)   // 27648

__global__ void __launch_bounds__(256) gemm2_mma(
        const float* __restrict__ W,
        const float* __restrict__ as, const float* __restrict__ ad) {
    extern __shared__ char smem[];
    uint32_t sb = smem_u32(smem);
    int tid = threadIdx.x;
    int w = tid >> 5, lane = tid & 31;
    int g = lane >> 2, tg = lane & 3;
    int blk = blockIdx.x;

    float acc[8][4];
#pragma unroll
    for (int nt = 0; nt < 8; nt++)
#pragma unroll
        for (int q = 0; q < 4; q++) acc[nt][q] = 0.f;

    uint32_t* sA = (uint32_t*)(smem + SM2_A);
    uint32_t* sB = (uint32_t*)(smem + SM2_B);

    for (int kc = 0; kc < 2; kc++) {
        for (int i = tid; i < 128 * 16; i += 256) {
            int row = i >> 4, q = i & 15;
            int rg = blk * 128 + row; if (rg >= NNODE) rg = NNODE - 1;
            float4 v = __ldg((const float4*)(g_h2 + (size_t)rg * C1 + kc * 64) + q);
            int o = row * (SA_STRIDE / 2) + q * 2;
            sA[o]     = pack_f16(v.x, v.y);
            sA[o + 1] = pack_f16(v.z, v.w);
        }
        for (int i = tid; i < 64 * 16; i += 256) {
            int kk = i >> 4, q = i & 15;
            float4 v = __ldg((const float4*)(W + (size_t)(kc * 64 + kk) * C2) + q);
            int o = kk * (SB2_STRIDE / 2) + q * 2;
            sB[o]     = pack_f16(v.x, v.y);
            sB[o + 1] = pack_f16(v.z, v.w);
        }
        __syncthreads();

#pragma unroll
        for (int sub = 0; sub < 4; sub++) {
            int kbase = sub * 16;
            int ar = w * 16 + (lane & 15);
            int ak = kbase + ((lane >> 4) << 3);
            uint32_t aoff = (uint32_t)(ar * SA_STRIDE + ak) * 2;
            uint32_t af[4];
            asm volatile("ldmatrix.sync.aligned.m8n8.x4.shared.b16 {%0,%1,%2,%3}, [%4];"
                : "=r"(af[0]), "=r"(af[1]), "=r"(af[2]), "=r"(af[3])
                : "r"(sb + SM2_A + aoff));
#pragma unroll
            for (int nt = 0; nt < 8; nt++) {
                uint32_t boff = (uint32_t)((kbase + (lane & 15)) * SB2_STRIDE + nt * 8) * 2;
                uint32_t b0, b1;
                asm volatile("ldmatrix.sync.aligned.m8n8.x2.trans.shared.b16 {%0,%1}, [%2];"
                    : "=r"(b0), "=r"(b1) : "r"(sb + SM2_B + boff));
                mma16816h(acc[nt], af, b0, b1);
            }
        }
        __syncthreads();
    }

    int rowA = blk * 128 + w * 16 + g;
    float sp0 = 0.f, dp0 = 0.f, sp1 = 0.f, dp1 = 0.f;
#pragma unroll
    for (int nt = 0; nt < 8; nt++) {
        int c0 = nt * 8 + tg * 2;
        float a0 = __ldg(as + c0), a1 = __ldg(as + c0 + 1);
        float d0 = __ldg(ad + c0), d1 = __ldg(ad + c0 + 1);
        sp0 += acc[nt][0] * a0 + acc[nt][1] * a1;
        dp0 += acc[nt][0] * d0 + acc[nt][1] * d1;
        sp1 += acc[nt][2] * a0 + acc[nt][3] * a1;
        dp1 += acc[nt][2] * d0 + acc[nt][3] * d1;
        if (rowA < NNODE)
            *(__half2*)(g_h3 + (size_t)rowA * C2 + c0) = __floats2half2_rn(acc[nt][0], acc[nt][1]);
        if (rowA + 8 < NNODE)
            *(__half2*)(g_h3 + (size_t)(rowA + 8) * C2 + c0) = __floats2half2_rn(acc[nt][2], acc[nt][3]);
    }
    sp0 += __shfl_xor_sync(0xffffffffu, sp0, 1); sp0 += __shfl_xor_sync(0xffffffffu, sp0, 2);
    dp0 += __shfl_xor_sync(0xffffffffu, dp0, 1); dp0 += __shfl_xor_sync(0xffffffffu, dp0, 2);
    sp1 += __shfl_xor_sync(0xffffffffu, sp1, 1); sp1 += __shfl_xor_sync(0xffffffffu, sp1, 2);
    dp1 += __shfl_xor_sync(0xffffffffu, dp1, 1); dp1 += __shfl_xor_sync(0xffffffffu, dp1, 2);
    if (tg == 0) {
        if (rowA < NNODE)     { g_als2[rowA] = sp0;     g_ald2[rowA] = dp0; }
        if (rowA + 8 < NNODE) { g_als2[rowA + 8] = sp1; g_ald2[rowA + 8] = dp1; }
    }
}

// ---------------- CSR build ----------------
__global__ void zero_deg() {
    int i = blockIdx.x * blockDim.x + threadIdx.x;
    if (i < NNODE) g_deg[i] = 0;
}

__global__ void hist(const int* __restrict__ ei, int E, int ET) {
    int i = blockIdx.x * blockDim.x + threadIdx.x;
    if (i >= ET) return;
    int d = (i < E) ? __ldg(ei + E + i) : i - E;
    atomicAdd(&g_deg[d], 1);
}

__global__ void scanA() {
    int i = blockIdx.x * 1024 + threadIdx.x;
    int v = (i < NNODE) ? g_deg[i] : 0;
    int lane = threadIdx.x & 31, wid = threadIdx.x >> 5;
    int x = v;
#pragma unroll
    for (int o = 1; o < 32; o <<= 1) {
        int t = __shfl_up_sync(0xffffffffu, x, o);
        if (lane >= o) x += t;
    }
    __shared__ int ws[32];
    if (lane == 31) ws[wid] = x;
    __syncthreads();
    if (wid == 0) {
        int y = ws[lane];
#pragma unroll
        for (int o = 1; o < 32; o <<= 1) {
            int t = __shfl_up_sync(0xffffffffu, y, o);
            if (lane >= o) y += t;
        }
        ws[lane] = y;
    }
    __syncthreads();
    int excl = x - v + (wid > 0 ? ws[wid - 1] : 0);
    if (i < NNODE) g_roff[i] = excl;
    if (threadIdx.x == 0) g_bsum[blockIdx.x] = ws[31];
}

__global__ void scanB(int nb) {
    int t = threadIdx.x;
    int v = (t < nb) ? g_bsum[t] : 0;
    int lane = t & 31, wid = t >> 5;
    int x = v;
#pragma unroll
    for (int o = 1; o < 32; o <<= 1) {
        int u = __shfl_up_sync(0xffffffffu, x, o);
        if (lane >= o) x += u;
    }
    __shared__ int ws[8];
    if (lane == 31) ws[wid] = x;
    __syncthreads();
    int carry = 0;
    for (int k = 0; k < wid; k++) carry += ws[k];
    int excl = x - v + carry;
    if (t < nb) g_bsum[t] = excl;
}

__global__ void scanC() {
    int i = blockIdx.x * blockDim.x + threadIdx.x;
    if (i >= NNODE) return;
    int r = g_roff[i] + g_bsum[i >> 10];
    g_roff[i] = r;
    g_cur[i]  = r;
}

__global__ void scatter(const int* __restrict__ ei, int E, int ET) {
    int i = blockIdx.x * blockDim.x + threadIdx.x;
    if (i >= ET) return;
    int s, d;
    if (i < E) { s = __ldg(ei + i); d = __ldg(ei + E + i); } else { s = d = i - E; }
    int p = atomicAdd(&g_cur[d], 1);
    g_csr[p] = s;
}

// ---------------- layer-1 aggregation: depth-2 pipelined gather ----------------
__global__ void __launch_bounds__(256) agg1(const float* __restrict__ b1) {
    int n = (int)((blockIdx.x * blockDim.x + threadIdx.x) >> 5);
    if (n >= NNODE) return;
    int lane = threadIdx.x & 31;
    int head = lane >> 4;
    int start = g_roff[n], len = g_deg[n];
    float aldv = __ldg(&g_ald1[n * 2 + head]);
    const int* cp = g_csr + start;

    float4 acc = make_float4(0.f, 0.f, 0.f, 0.f);
    float z = 0.f;

    int s0, s1 = 0;
    float al0, al1 = 0.f;
    uint2 u0, u1 = make_uint2(0u, 0u);
    s0 = __ldg(cp);
    al0 = __ldg(&g_als1[s0 * 2 + head]);
    u0 = *(const uint2*)(g_h1 + (size_t)s0 * C1 + lane * 4);
    if (len > 1) {
        s1 = __ldg(cp + 1);
        al1 = __ldg(&g_als1[s1 * 2 + head]);
        u1 = *(const uint2*)(g_h1 + (size_t)s1 * C1 + lane * 4);
    }
    for (int j = 0; j < len; j++) {
        int s2 = 0; float al2 = 0.f; uint2 u2 = make_uint2(0u, 0u);
        if (j + 2 < len) {
            s2 = __ldg(cp + j + 2);
            al2 = __ldg(&g_als1[s2 * 2 + head]);
            u2 = *(const uint2*)(g_h1 + (size_t)s2 * C1 + lane * 4);
        }
        float w = expf(leaky(al0 + aldv));
        float2 f0 = __half22float2(*(__half2*)&u0.x);
        float2 f1 = __half22float2(*(__half2*)&u0.y);
        acc.x = fmaf(w, f0.x, acc.x);
        acc.y = fmaf(w, f0.y, acc.y);
        acc.z = fmaf(w, f1.x, acc.z);
        acc.w = fmaf(w, f1.y, acc.w);
        z += w;
        s0 = s1; al0 = al1; u0 = u1;
        s1 = s2; al1 = al2; u1 = u2;
    }
    float inv = 1.f / z;
    float4 bv = __ldg((const float4*)b1 + lane);
    float o0 = fmaf(acc.x, inv, bv.x);
    float o1 = fmaf(acc.y, inv, bv.y);
    float o2 = fmaf(acc.z, inv, bv.z);
    float o3 = fmaf(acc.w, inv, bv.w);
    o0 = o0 > 0.f ? o0 : expm1f(o0);
    o1 = o1 > 0.f ? o1 : expm1f(o1);
    o2 = o2 > 0.f ? o2 : expm1f(o2);
    o3 = o3 > 0.f ? o3 : expm1f(o3);
    *(float4*)(g_h2 + (size_t)n * C1 + lane * 4) = make_float4(o0, o1, o2, o3);
}

// ---------------- layer-2 aggregation: depth-2 pipelined, 2 edges/warp ----------------
__global__ void __launch_bounds__(256) agg2(float* __restrict__ out,
                                            const float* __restrict__ b2) {
    int n = (int)((blockIdx.x * blockDim.x + threadIdx.x) >> 5);
    if (n >= NNODE) return;
    int lane = threadIdx.x & 31;
    int half = lane >> 4, l = lane & 15;
    int start = g_roff[n], len = g_deg[n];
    float aldv = __ldg(&g_ald2[n]);
    const int* cp = g_csr + start;

    float4 acc = make_float4(0.f, 0.f, 0.f, 0.f);
    float z = 0.f;

    int s0 = 0, s1 = 0;
    float al0 = 0.f, al1 = 0.f;
    uint2 u0 = make_uint2(0u, 0u), u1 = make_uint2(0u, 0u);
    if (half < len) {
        s0 = __ldg(cp + half);
        al0 = __ldg(&g_als2[s0]);
        u0 = *(const uint2*)(g_h3 + (size_t)s0 * C2 + l * 4);
    }
    if (half + 2 < len) {
        s1 = __ldg(cp + half + 2);
        al1 = __ldg(&g_als2[s1]);
        u1 = *(const uint2*)(g_h3 + (size_t)s1 * C2 + l * 4);
    }
    for (int j = half; j < len; j += 2) {
        int s2 = 0; float al2 = 0.f; uint2 u2 = make_uint2(0u, 0u);
        if (j + 4 < len) {
            s2 = __ldg(cp + j + 4);
            al2 = __ldg(&g_als2[s2]);
            u2 = *(const uint2*)(g_h3 + (size_t)s2 * C2 + l * 4);
        }
        float w = expf(leaky(al0 + aldv));
        float2 f0 = __half22float2(*(__half2*)&u0.x);
        float2 f1 = __half22float2(*(__half2*)&u0.y);
        acc.x = fmaf(w, f0.x, acc.x);
        acc.y = fmaf(w, f0.y, acc.y);
        acc.z = fmaf(w, f1.x, acc.z);
        acc.w = fmaf(w, f1.y, acc.w);
        z += w;
        s0 = s1; al0 = al1; u0 = u1;
        s1 = s2; al1 = al2; u1 = u2;
    }
    acc.x += __shfl_xor_sync(0xffffffffu, acc.x, 16);
    acc.y += __shfl_xor_sync(0xffffffffu, acc.y, 16);
    acc.z += __shfl_xor_sync(0xffffffffu, acc.z, 16);
    acc.w += __shfl_xor_sync(0xffffffffu, acc.w, 16);
    z     += __shfl_xor_sync(0xffffffffu, z, 16);
    if (half == 0) {
        float inv = 1.f / z;
        float4 bv = __ldg((const float4*)b2 + l);
        *(float4*)(out + (size_t)n * C2 + l * 4) =
            make_float4(fmaf(acc.x, inv, bv.x), fmaf(acc.y, inv, bv.y),
                        fmaf(acc.z, inv, bv.z), fmaf(acc.w, inv, bv.w));
    }
}

// ---------------- launch ----------------
extern "C" void kernel_launch(void* const* d_in, const int* in_sizes, int n_in,
                              void* d_out, int out_size) {
    const float* x      = (const float*)d_in[0];
    const int*   ei     = (const int*)  d_in[1];
    const float* W1     = (const float*)d_in[2];
    const float* a_src1 = (const float*)d_in[3];
    const float* a_dst1 = (const float*)d_in[4];
    const float* b1     = (const float*)d_in[5];
    const float* W2     = (const float*)d_in[6];
    const float* a_src2 = (const float*)d_in[7];
    const float* a_dst2 = (const float*)d_in[8];
    const float* b2     = (const float*)d_in[9];
    float* out = (float*)d_out;

    const int E = in_sizes[1] / 2;
    const int ET = E + NNODE;
    const int TB = 256;
    const int nbScan = (NNODE + 1023) / 1024;

    static cudaStream_t sCsr = nullptr;
    static cudaEvent_t evFork = nullptr, evJoin = nullptr;
    static int forkOk = -1;
    if (forkOk == -1) {
        cudaFuncSetAttribute(gemm1_mma, cudaFuncAttributeMaxDynamicSharedMemorySize, G1_SMEM);
        cudaFuncSetAttribute(gemm2_mma, cudaFuncAttributeMaxDynamicSharedMemorySize, G2_SMEM);
        cudaError_t e1 = cudaStreamCreateWithFlags(&sCsr, cudaStreamNonBlocking);
        cudaError_t e2 = cudaEventCreateWithFlags(&evFork, cudaEventDisableTiming);
        cudaError_t e3 = cudaEventCreateWithFlags(&evJoin, cudaEventDisableTiming);
        forkOk = (e1 == cudaSuccess && e2 == cudaSuccess && e3 == cudaSuccess) ? 1 : 0;
    }

    if (forkOk == 1) {
        cudaEventRecord(evFork, 0);
        cudaStreamWaitEvent(sCsr, evFork, 0);

        zero_deg<<<(NNODE + TB - 1) / TB, TB, 0, sCsr>>>();
        hist<<<(ET + TB - 1) / TB, TB, 0, sCsr>>>(ei, E, ET);
        scanA<<<nbScan, 1024, 0, sCsr>>>();
        scanB<<<1, 256, 0, sCsr>>>(nbScan);
        scanC<<<(NNODE + TB - 1) / TB, TB, 0, sCsr>>>();
        scatter<<<(ET + TB - 1) / TB, TB, 0, sCsr>>>(ei, E, ET);
        cudaEventRecord(evJoin, sCsr);

        gemm1_mma<<<(NNODE + 127) / 128, 256, G1_SMEM>>>(x, W1, a_src1, a_dst1);

        cudaStreamWaitEvent(0, evJoin, 0);
    } else {
        zero_deg<<<(NNODE + TB - 1) / TB, TB>>>();
        hist<<<(ET + TB - 1) / TB, TB>>>(ei, E, ET);
        scanA<<<nbScan, 1024>>>();
        scanB<<<1, 256>>>(nbScan);
        scanC<<<(NNODE + TB - 1) / TB, TB>>>();
        scatter<<<(ET + TB - 1) / TB, TB>>>(ei, E, ET);
        gemm1_mma<<<(NNODE + 127) / 128, 256, G1_SMEM>>>(x, W1, a_src1, a_dst1);
    }

    agg1<<<(NNODE * 32 + TB - 1) / TB, TB>>>(b1);

    gemm2_mma<<<(NNODE + 127) / 128, 256, G2_SMEM>>>(W2, a_src2, a_dst2);
    agg2<<<(NNODE * 32 + TB - 1) / TB, TB>>>(out, b2);
}